// round 1
// baseline (speedup 1.0000x reference)
#include <cuda_runtime.h>
#include <math.h>

#define N_NODES  100000
#define N_EDGES  1600000
#define NH       128
#define N_GRAPHS 512
#define N_CLASS  10
#define TM       16

// -------- scratch (device globals; no allocation allowed) --------
__device__ float g_bufA[N_NODES * NH];
__device__ float g_bufB[N_NODES * NH];
__device__ float g_dinv[N_NODES];
__device__ int   g_deg[N_NODES];
__device__ float g_sums[N_GRAPHS * NH];
__device__ int   g_cnt[N_GRAPHS];

// -------- init: deg=1 (self loop), sums=0, cnt=0 --------
__global__ void k_init() {
    int i = blockIdx.x * blockDim.x + threadIdx.x;
    if (i < N_NODES) g_deg[i] = 1;
    if (i < N_GRAPHS * NH) g_sums[i] = 0.f;
    if (i < N_GRAPHS) g_cnt[i] = 0;
}

__global__ void k_count(const int* __restrict__ dst) {
    int e = blockIdx.x * blockDim.x + threadIdx.x;
    if (e < N_EDGES) atomicAdd(&g_deg[dst[e]], 1);
}

__global__ void k_dinv() {
    int i = blockIdx.x * blockDim.x + threadIdx.x;
    if (i < N_NODES) g_dinv[i] = rsqrtf((float)g_deg[i]);
}

// -------- GEMM: C[M,128] = A[M,128] @ W[128,128], M = N_NODES --------
// block = 128 threads, computes TM=16 rows; W staged in 32-row K chunks.
__global__ void k_gemm(const float* __restrict__ A, const float* __restrict__ W,
                       float* __restrict__ C) {
    __shared__ float sW[32 * NH];   // 16 KB
    __shared__ float sA[TM * NH];   // 8 KB
    int t = threadIdx.x;            // 0..127 -> output column
    long row0 = (long)blockIdx.x * TM;

    // stage A tile (16 rows x 128) as float4
    const float4* A4 = (const float4*)(A + row0 * NH);
    float4* sA4 = (float4*)sA;
    for (int i = t; i < TM * NH / 4; i += 128) sA4[i] = A4[i];

    float acc[TM];
#pragma unroll
    for (int r = 0; r < TM; r++) acc[r] = 0.f;

    const float4* W4 = (const float4*)W;
    float4* sW4 = (float4*)sW;

    for (int kc = 0; kc < NH; kc += 32) {
        __syncthreads();
        for (int i = t; i < 32 * NH / 4; i += 128)
            sW4[i] = W4[(long)kc * (NH / 4) + i];
        __syncthreads();
#pragma unroll 4
        for (int k2 = 0; k2 < 32; k2++) {
            float w = sW[k2 * NH + t];
#pragma unroll
            for (int r = 0; r < TM; r++)
                acc[r] += sA[r * NH + (kc + k2)] * w;
        }
    }
#pragma unroll
    for (int r = 0; r < TM; r++) C[(row0 + r) * NH + t] = acc[r];
}

// -------- scatter: self-loop init  out[i] = in[i] * dinv[i]^2 --------
__global__ void k_selfinit(const float* __restrict__ in, float* __restrict__ out) {
    int idx = blockIdx.x * blockDim.x + threadIdx.x;
    if (idx < N_NODES * NH) {
        int n = idx >> 7;
        float dv = g_dinv[n];
        out[idx] = in[idx] * dv * dv;
    }
}

// -------- scatter: edges, one warp per edge, float4 gather + 4 atomics/lane --------
__global__ void k_scatter(const float* __restrict__ in, float* __restrict__ out,
                          const int* __restrict__ srcp, const int* __restrict__ dstp) {
    int warp = (int)((blockIdx.x * (long)blockDim.x + threadIdx.x) >> 5);
    int lane = threadIdx.x & 31;
    if (warp >= N_EDGES) return;
    int s = srcp[warp], d = dstp[warp];
    float nrm = g_dinv[s] * g_dinv[d];
    float4 v = ((const float4*)(in + (long)s * NH))[lane];
    float* o = out + (long)d * NH + lane * 4;
    atomicAdd(o + 0, v.x * nrm);
    atomicAdd(o + 1, v.y * nrm);
    atomicAdd(o + 2, v.z * nrm);
    atomicAdd(o + 3, v.w * nrm);
}

// -------- layer-1 epilogue: +b1, BN(eval), ReLU --------
__global__ void k_post1(const float* __restrict__ in, float* __restrict__ out,
                        const float* __restrict__ b1, const float* __restrict__ gamma,
                        const float* __restrict__ beta) {
    int idx = blockIdx.x * blockDim.x + threadIdx.x;
    if (idx < N_NODES * NH) {
        int c = idx & 127;
        float gs = gamma[c] * rsqrtf(1.0f + 1e-5f);
        float v = (in[idx] + b1[c]) * gs + beta[c];
        out[idx] = fmaxf(v, 0.f);
    }
}

// -------- mean-pool accumulation: sums[batch[n]] += h2[n] + b2 --------
__global__ void k_pool(const float* __restrict__ in, const int* __restrict__ batch,
                       const float* __restrict__ b2) {
    int idx = blockIdx.x * blockDim.x + threadIdx.x;
    if (idx < N_NODES * NH) {
        int n = idx >> 7, c = idx & 127;
        int b = batch[n];
        atomicAdd(&g_sums[b * NH + c], in[idx] + b2[c]);
        if (c == 0) atomicAdd(&g_cnt[b], 1);
    }
}

// -------- classifier + log_softmax; one block (128 threads) per graph --------
__global__ void k_final(const float* __restrict__ clsW, const float* __restrict__ clsb,
                        float* __restrict__ out) {
    int gph = blockIdx.x;
    int t = threadIdx.x;
    __shared__ float sg[NH];
    __shared__ float sl[N_CLASS];
    __shared__ float lse;
    float cnt = fmaxf((float)g_cnt[gph], 1.0f);
    float gv = g_sums[gph * NH + t] / cnt;
    sg[t] = gv;
    out[N_GRAPHS * N_CLASS + gph * NH + t] = gv;   // g output
    __syncthreads();
    if (t < N_CLASS) {
        float acc = clsb[t];
        for (int k = 0; k < NH; k++) acc += sg[k] * clsW[k * N_CLASS + t];
        sl[t] = acc;
    }
    __syncthreads();
    if (t == 0) {
        float m = sl[0];
        for (int i = 1; i < N_CLASS; i++) m = fmaxf(m, sl[i]);
        float s = 0.f;
        for (int i = 0; i < N_CLASS; i++) s += expf(sl[i] - m);
        lse = m + logf(s);
    }
    __syncthreads();
    if (t < N_CLASS) out[gph * N_CLASS + t] = sl[t] - lse;  // log_softmax output
}

extern "C" void kernel_launch(void* const* d_in, const int* in_sizes, int n_in,
                              void* d_out, int out_size) {
    const float* x     = (const float*)d_in[0];
    const int*   ei    = (const int*)d_in[1];
    const int*   batch = (const int*)d_in[2];
    const float* W1    = (const float*)d_in[3];
    const float* b1    = (const float*)d_in[4];
    const float* gamma = (const float*)d_in[5];
    const float* beta  = (const float*)d_in[6];
    const float* W2    = (const float*)d_in[7];
    const float* b2    = (const float*)d_in[8];
    const float* clsW  = (const float*)d_in[9];
    const float* clsb  = (const float*)d_in[10];
    float* out = (float*)d_out;

    const int* srcp = ei;            // edge_index[0]
    const int* dstp = ei + N_EDGES;  // edge_index[1]

    float *bufA, *bufB;
    cudaGetSymbolAddress((void**)&bufA, g_bufA);
    cudaGetSymbolAddress((void**)&bufB, g_bufB);

    const int TPB = 256;
    int nodeBlocks = (N_NODES + TPB - 1) / TPB;
    int edgeBlocks = (N_EDGES + TPB - 1) / TPB;
    int elemBlocks = (N_NODES * NH + TPB - 1) / TPB;
    long scatterThreads = (long)N_EDGES * 32;
    int scatterBlocks = (int)((scatterThreads + TPB - 1) / TPB);

    // normalization
    k_init<<<elemBlocks, TPB>>>();
    k_count<<<edgeBlocks, TPB>>>(dstp);
    k_dinv<<<nodeBlocks, TPB>>>();

    // layer 1
    k_gemm<<<N_NODES / TM, 128>>>(x, W1, bufA);
    k_selfinit<<<elemBlocks, TPB>>>(bufA, bufB);
    k_scatter<<<scatterBlocks, TPB>>>(bufA, bufB, srcp, dstp);
    k_post1<<<elemBlocks, TPB>>>(bufB, bufA, b1, gamma, beta);

    // layer 2
    k_gemm<<<N_NODES / TM, 128>>>(bufA, W2, bufB);
    k_selfinit<<<elemBlocks, TPB>>>(bufB, bufA);
    k_scatter<<<scatterBlocks, TPB>>>(bufB, bufA, srcp, dstp);

    // pooling + classifier
    k_pool<<<elemBlocks, TPB>>>(bufA, batch, b2);
    k_final<<<N_GRAPHS, NH>>>(clsW, clsb, out);
}

// round 2
// speedup vs baseline: 2.7750x; 2.7750x over previous
#include <cuda_runtime.h>
#include <math.h>

#define N_NODES  100000
#define N_EDGES  1600000
#define NH       128
#define N_GRAPHS 512
#define N_CLASS  10
#define GR       64          // rows per GEMM block
#define SCAN_B   1024
#define SCAN_G   98          // ceil(100000/1024)

// -------- scratch (device globals; no allocation allowed) --------
__device__ float g_bufA[N_NODES * NH];
__device__ float g_bufB[N_NODES * NH];
__device__ float g_dinv[N_NODES];
__device__ int   g_deg[N_NODES];       // 1 + in-degree (self loop)
__device__ int   g_rowStart[N_NODES];  // CSR row offsets (exclusive scan of deg-1)
__device__ int   g_cursor[N_NODES];
__device__ int   g_esrc[N_EDGES];      // edge sources sorted by dst
__device__ float g_enorm[N_EDGES];     // dinv[src]*dinv[dst] sorted by dst
__device__ int   g_bsum[128];
__device__ int   g_boff[128];
__device__ float g_sums[N_GRAPHS * NH];
__device__ int   g_cnt[N_GRAPHS];

// ================= setup =================
__global__ void k_init() {
    int i = blockIdx.x * blockDim.x + threadIdx.x;
    if (i < N_NODES) { g_deg[i] = 1; g_cursor[i] = 0; }
    if (i < N_GRAPHS * NH) g_sums[i] = 0.f;
    if (i < N_GRAPHS) g_cnt[i] = 0;
}

__global__ void k_count(const int* __restrict__ dst) {
    int e = blockIdx.x * blockDim.x + threadIdx.x;
    if (e < N_EDGES) atomicAdd(&g_deg[dst[e]], 1);
}

__global__ void k_dinv(const int* __restrict__ batch) {
    int i = blockIdx.x * blockDim.x + threadIdx.x;
    if (i < N_NODES) {
        g_dinv[i] = rsqrtf((float)g_deg[i]);
        atomicAdd(&g_cnt[batch[i]], 1);
    }
}

// ---- exclusive scan of (deg-1) -> g_rowStart ----
__global__ void k_scanA() {
    __shared__ int s[SCAN_B];
    int t = threadIdx.x;
    int i = blockIdx.x * SCAN_B + t;
    int v = (i < N_NODES) ? (g_deg[i] - 1) : 0;
    s[t] = v;
    __syncthreads();
    for (int off = 1; off < SCAN_B; off <<= 1) {
        int add = (t >= off) ? s[t - off] : 0;
        __syncthreads();
        s[t] += add;
        __syncthreads();
    }
    if (i < N_NODES) g_rowStart[i] = s[t] - v;          // exclusive
    if (t == SCAN_B - 1) g_bsum[blockIdx.x] = s[t];
}

__global__ void k_scanB() {
    int run = 0;
    for (int b = 0; b < SCAN_G; b++) { g_boff[b] = run; run += g_bsum[b]; }
}

__global__ void k_scanC() {
    int i = blockIdx.x * SCAN_B + threadIdx.x;
    if (i < N_NODES) g_rowStart[i] += g_boff[blockIdx.x];
}

__global__ void k_fill(const int* __restrict__ srcp, const int* __restrict__ dstp) {
    int e = blockIdx.x * blockDim.x + threadIdx.x;
    if (e < N_EDGES) {
        int s = srcp[e], d = dstp[e];
        int pos = g_rowStart[d] + atomicAdd(&g_cursor[d], 1);
        g_esrc[pos] = s;
        g_enorm[pos] = g_dinv[s] * g_dinv[d];
    }
}

// ================= GEMM: C[M,128] = A[M,128] @ W[128,128] =================
// 256 threads, 64 rows/block, thread tile = 8 rows x 4 cols.
__global__ void k_gemm2(const float* __restrict__ A, const float* __restrict__ W,
                        float* __restrict__ C) {
    __shared__ float sA[GR][132];        // padded: no bank conflicts
    __shared__ float sW[32 * NH];
    int t  = threadIdx.x;
    int tx = t & 31;                     // col group: cols 4*tx..4*tx+3
    int ty = t >> 5;                     // row group: rows ty*8..ty*8+7
    long row0 = (long)blockIdx.x * GR;

    const float4* A4 = (const float4*)A;
    for (int i = t; i < GR * 32; i += 256) {
        int r = i >> 5, c = i & 31;
        long rg = row0 + r; if (rg > N_NODES - 1) rg = N_NODES - 1;
        float4 v = A4[rg * 32 + c];
        *(float4*)&sA[r][c * 4] = v;
    }

    float acc[8][4];
#pragma unroll
    for (int r = 0; r < 8; r++)
#pragma unroll
        for (int c = 0; c < 4; c++) acc[r][c] = 0.f;

    const float4* W4 = (const float4*)W;
    for (int kc = 0; kc < NH; kc += 32) {
        __syncthreads();
        for (int i = t; i < 32 * 32; i += 256)
            ((float4*)sW)[i] = W4[kc * 32 + i];
        __syncthreads();
#pragma unroll
        for (int k = 0; k < 32; k++) {
            float4 w = ((float4*)sW)[k * 32 + tx];
#pragma unroll
            for (int r = 0; r < 8; r++) {
                float a = sA[ty * 8 + r][kc + k];
                acc[r][0] += a * w.x; acc[r][1] += a * w.y;
                acc[r][2] += a * w.z; acc[r][3] += a * w.w;
            }
        }
    }
#pragma unroll
    for (int r = 0; r < 8; r++) {
        long rg = row0 + ty * 8 + r;
        if (rg < N_NODES) {
            float4 v = {acc[r][0], acc[r][1], acc[r][2], acc[r][3]};
            ((float4*)C)[rg * 32 + tx] = v;
        }
    }
}

// ============ gather layer 1: agg -> +b1 -> BN -> ReLU -> out ============
// warp per destination node, lane = float4 column chunk
__global__ void k_gather1(const float* __restrict__ in, float* __restrict__ out,
                          const float* __restrict__ b1, const float* __restrict__ gamma,
                          const float* __restrict__ beta) {
    int d = (int)((blockIdx.x * (long)blockDim.x + threadIdx.x) >> 5);
    int lane = threadIdx.x & 31;
    if (d >= N_NODES) return;
    int start = g_rowStart[d];
    int len   = g_deg[d] - 1;
    float dv  = g_dinv[d];
    const float4* in4 = (const float4*)in;
    float4 self = in4[(long)d * 32 + lane];
    float sc = dv * dv;
    float ax = self.x * sc, ay = self.y * sc, az = self.z * sc, aw = self.w * sc;

    int j = 0;
    for (; j + 4 <= len; j += 4) {
        int   s0 = g_esrc[start + j],     s1 = g_esrc[start + j + 1];
        int   s2 = g_esrc[start + j + 2], s3 = g_esrc[start + j + 3];
        float n0 = g_enorm[start + j],     n1 = g_enorm[start + j + 1];
        float n2 = g_enorm[start + j + 2], n3 = g_enorm[start + j + 3];
        float4 v0 = in4[(long)s0 * 32 + lane];
        float4 v1 = in4[(long)s1 * 32 + lane];
        float4 v2 = in4[(long)s2 * 32 + lane];
        float4 v3 = in4[(long)s3 * 32 + lane];
        ax += n0 * v0.x + n1 * v1.x + n2 * v2.x + n3 * v3.x;
        ay += n0 * v0.y + n1 * v1.y + n2 * v2.y + n3 * v3.y;
        az += n0 * v0.z + n1 * v1.z + n2 * v2.z + n3 * v3.z;
        aw += n0 * v0.w + n1 * v1.w + n2 * v2.w + n3 * v3.w;
    }
    for (; j < len; j++) {
        int s = g_esrc[start + j];
        float n = g_enorm[start + j];
        float4 v = in4[(long)s * 32 + lane];
        ax += n * v.x; ay += n * v.y; az += n * v.z; aw += n * v.w;
    }

    int c4 = lane * 4;
    float4 bb = *(const float4*)&b1[c4];
    float4 gg = *(const float4*)&gamma[c4];
    float4 be = *(const float4*)&beta[c4];
    float inv = rsqrtf(1.0f + 1e-5f);
    float4 o;
    o.x = fmaxf((ax + bb.x) * (gg.x * inv) + be.x, 0.f);
    o.y = fmaxf((ay + bb.y) * (gg.y * inv) + be.y, 0.f);
    o.z = fmaxf((az + bb.z) * (gg.z * inv) + be.z, 0.f);
    o.w = fmaxf((aw + bb.w) * (gg.w * inv) + be.w, 0.f);
    ((float4*)out)[(long)d * 32 + lane] = o;
}

// ========= gather layer 2: agg -> +b2 -> atomic pool into g_sums =========
__global__ void k_gather2(const float* __restrict__ in, const float* __restrict__ b2,
                          const int* __restrict__ batch) {
    int d = (int)((blockIdx.x * (long)blockDim.x + threadIdx.x) >> 5);
    int lane = threadIdx.x & 31;
    if (d >= N_NODES) return;
    int start = g_rowStart[d];
    int len   = g_deg[d] - 1;
    float dv  = g_dinv[d];
    const float4* in4 = (const float4*)in;
    float4 self = in4[(long)d * 32 + lane];
    float sc = dv * dv;
    float ax = self.x * sc, ay = self.y * sc, az = self.z * sc, aw = self.w * sc;

    int j = 0;
    for (; j + 4 <= len; j += 4) {
        int   s0 = g_esrc[start + j],     s1 = g_esrc[start + j + 1];
        int   s2 = g_esrc[start + j + 2], s3 = g_esrc[start + j + 3];
        float n0 = g_enorm[start + j],     n1 = g_enorm[start + j + 1];
        float n2 = g_enorm[start + j + 2], n3 = g_enorm[start + j + 3];
        float4 v0 = in4[(long)s0 * 32 + lane];
        float4 v1 = in4[(long)s1 * 32 + lane];
        float4 v2 = in4[(long)s2 * 32 + lane];
        float4 v3 = in4[(long)s3 * 32 + lane];
        ax += n0 * v0.x + n1 * v1.x + n2 * v2.x + n3 * v3.x;
        ay += n0 * v0.y + n1 * v1.y + n2 * v2.y + n3 * v3.y;
        az += n0 * v0.z + n1 * v1.z + n2 * v2.z + n3 * v3.z;
        aw += n0 * v0.w + n1 * v1.w + n2 * v2.w + n3 * v3.w;
    }
    for (; j < len; j++) {
        int s = g_esrc[start + j];
        float n = g_enorm[start + j];
        float4 v = in4[(long)s * 32 + lane];
        ax += n * v.x; ay += n * v.y; az += n * v.z; aw += n * v.w;
    }

    int c4 = lane * 4;
    float4 bb = *(const float4*)&b2[c4];
    int b = batch[d];
    float* sdst = &g_sums[b * NH + c4];
    atomicAdd(sdst + 0, ax + bb.x);
    atomicAdd(sdst + 1, ay + bb.y);
    atomicAdd(sdst + 2, az + bb.z);
    atomicAdd(sdst + 3, aw + bb.w);
}

// ========= classifier + log_softmax; one block (128 threads) per graph =========
__global__ void k_final(const float* __restrict__ clsW, const float* __restrict__ clsb,
                        float* __restrict__ out) {
    int gph = blockIdx.x;
    int t = threadIdx.x;
    __shared__ float sg[NH];
    __shared__ float sl[N_CLASS];
    __shared__ float lse;
    float cnt = fmaxf((float)g_cnt[gph], 1.0f);
    float gv = g_sums[gph * NH + t] / cnt;
    sg[t] = gv;
    out[N_GRAPHS * N_CLASS + gph * NH + t] = gv;   // g output
    __syncthreads();
    if (t < N_CLASS) {
        float acc = clsb[t];
        for (int k = 0; k < NH; k++) acc += sg[k] * clsW[k * N_CLASS + t];
        sl[t] = acc;
    }
    __syncthreads();
    if (t == 0) {
        float m = sl[0];
        for (int i = 1; i < N_CLASS; i++) m = fmaxf(m, sl[i]);
        float s = 0.f;
        for (int i = 0; i < N_CLASS; i++) s += expf(sl[i] - m);
        lse = m + logf(s);
    }
    __syncthreads();
    if (t < N_CLASS) out[gph * N_CLASS + t] = sl[t] - lse;  // log_softmax
}

extern "C" void kernel_launch(void* const* d_in, const int* in_sizes, int n_in,
                              void* d_out, int out_size) {
    const float* x     = (const float*)d_in[0];
    const int*   ei    = (const int*)d_in[1];
    const int*   batch = (const int*)d_in[2];
    const float* W1    = (const float*)d_in[3];
    const float* b1    = (const float*)d_in[4];
    const float* gamma = (const float*)d_in[5];
    const float* beta  = (const float*)d_in[6];
    const float* W2    = (const float*)d_in[7];
    const float* b2    = (const float*)d_in[8];
    const float* clsW  = (const float*)d_in[9];
    const float* clsb  = (const float*)d_in[10];
    float* out = (float*)d_out;

    const int* srcp = ei;            // edge_index[0]
    const int* dstp = ei + N_EDGES;  // edge_index[1]

    float *bufA, *bufB;
    cudaGetSymbolAddress((void**)&bufA, g_bufA);
    cudaGetSymbolAddress((void**)&bufB, g_bufB);

    const int TPB = 256;
    int nodeBlocks = (N_NODES + TPB - 1) / TPB;
    int edgeBlocks = (N_EDGES + TPB - 1) / TPB;
    int gemmBlocks = (N_NODES + GR - 1) / GR;
    int gatherBlocks = (N_NODES * 32 + TPB - 1) / TPB;

    // ---- CSR + norm setup ----
    k_init<<<nodeBlocks, TPB>>>();
    k_count<<<edgeBlocks, TPB>>>(dstp);
    k_dinv<<<nodeBlocks, TPB>>>(batch);
    k_scanA<<<SCAN_G, SCAN_B>>>();
    k_scanB<<<1, 1>>>();
    k_scanC<<<SCAN_G, SCAN_B>>>();
    k_fill<<<edgeBlocks, TPB>>>(srcp, dstp);

    // ---- layer 1 ----
    k_gemm2<<<gemmBlocks, 256>>>(x, W1, bufA);
    k_gather1<<<gatherBlocks, TPB>>>(bufA, bufB, b1, gamma, beta);

    // ---- layer 2 ----
    k_gemm2<<<gemmBlocks, 256>>>(bufB, W2, bufA);
    k_gather2<<<gatherBlocks, TPB>>>(bufA, b2, batch);

    // ---- classifier ----
    k_final<<<N_GRAPHS, NH>>>(clsW, clsb, out);
}

// round 3
// speedup vs baseline: 3.3697x; 1.2143x over previous
#include <cuda_runtime.h>
#include <cuda_fp16.h>
#include <math.h>

#define N_NODES  100000
#define N_EDGES  1600000
#define NH       128
#define N_GRAPHS 512
#define N_CLASS  10
#define GR       64          // rows per GEMM block
#define SCAN_B   1024
#define SCAN_G   98          // ceil(100000/1024)

struct alignas(8) h4 { __half2 a, b; };   // 4 halves = 8 bytes

// -------- scratch (device globals; no allocation allowed) --------
__device__ __half g_h1[N_NODES * NH];   // XW1 in fp16
__device__ __half g_h2[N_NODES * NH];   // H (post BN/ReLU) in fp16
__device__ float g_dinv[N_NODES];
__device__ int   g_deg[N_NODES];        // 1 + in-degree (self loop)
__device__ int   g_rowStart[N_NODES];
__device__ int   g_cursor[N_NODES];
__device__ int2  g_epack[N_EDGES];      // {src, norm-as-int} sorted by dst
__device__ int   g_bsum[128];
__device__ int   g_boff[128];
__device__ float g_sums[N_GRAPHS * NH]; // pooled sums of (A_hat @ H)
__device__ int   g_cnt[N_GRAPHS];

// ================= setup =================
__global__ void k_init() {
    int i = blockIdx.x * blockDim.x + threadIdx.x;
    if (i < N_NODES) { g_deg[i] = 1; g_cursor[i] = 0; }
    if (i < N_GRAPHS * NH) g_sums[i] = 0.f;
    if (i < N_GRAPHS) g_cnt[i] = 0;
}

__global__ void k_count(const int* __restrict__ dst) {
    int e = blockIdx.x * blockDim.x + threadIdx.x;
    if (e < N_EDGES) atomicAdd(&g_deg[dst[e]], 1);
}

__global__ void k_dinv(const int* __restrict__ batch) {
    int i = blockIdx.x * blockDim.x + threadIdx.x;
    if (i < N_NODES) {
        g_dinv[i] = rsqrtf((float)g_deg[i]);
        atomicAdd(&g_cnt[batch[i]], 1);
    }
}

// ---- exclusive scan of (deg-1) -> g_rowStart ----
__global__ void k_scanA() {
    __shared__ int s[SCAN_B];
    int t = threadIdx.x;
    int i = blockIdx.x * SCAN_B + t;
    int v = (i < N_NODES) ? (g_deg[i] - 1) : 0;
    s[t] = v;
    __syncthreads();
    for (int off = 1; off < SCAN_B; off <<= 1) {
        int add = (t >= off) ? s[t - off] : 0;
        __syncthreads();
        s[t] += add;
        __syncthreads();
    }
    if (i < N_NODES) g_rowStart[i] = s[t] - v;
    if (t == SCAN_B - 1) g_bsum[blockIdx.x] = s[t];
}

__global__ void k_scanB() {
    int run = 0;
    for (int b = 0; b < SCAN_G; b++) { g_boff[b] = run; run += g_bsum[b]; }
}

__global__ void k_scanC() {
    int i = blockIdx.x * SCAN_B + threadIdx.x;
    if (i < N_NODES) g_rowStart[i] += g_boff[blockIdx.x];
}

__global__ void k_fill(const int* __restrict__ srcp, const int* __restrict__ dstp) {
    int e = blockIdx.x * blockDim.x + threadIdx.x;
    if (e < N_EDGES) {
        int s = srcp[e], d = dstp[e];
        int pos = g_rowStart[d] + atomicAdd(&g_cursor[d], 1);
        float nrm = g_dinv[s] * g_dinv[d];
        g_epack[pos] = make_int2(s, __float_as_int(nrm));
    }
}

// ============ GEMM1: g_h1[M,128] = x[M,128] @ W1[128,128]  (fp32 math, fp16 out) ============
__global__ void k_gemm1(const float* __restrict__ A, const float* __restrict__ W) {
    __shared__ float sA[GR][132];
    __shared__ float sW[32 * NH];
    int t  = threadIdx.x;
    int tx = t & 31;
    int ty = t >> 5;
    long row0 = (long)blockIdx.x * GR;

    const float4* A4 = (const float4*)A;
    for (int i = t; i < GR * 32; i += 256) {
        int r = i >> 5, c = i & 31;
        long rg = row0 + r; if (rg > N_NODES - 1) rg = N_NODES - 1;
        float4 v = A4[rg * 32 + c];
        *(float4*)&sA[r][c * 4] = v;
    }

    float acc[8][4];
#pragma unroll
    for (int r = 0; r < 8; r++)
#pragma unroll
        for (int c = 0; c < 4; c++) acc[r][c] = 0.f;

    const float4* W4 = (const float4*)W;
    for (int kc = 0; kc < NH; kc += 32) {
        __syncthreads();
        for (int i = t; i < 32 * 32; i += 256)
            ((float4*)sW)[i] = W4[kc * 32 + i];
        __syncthreads();
#pragma unroll
        for (int k = 0; k < 32; k++) {
            float4 w = ((float4*)sW)[k * 32 + tx];
#pragma unroll
            for (int r = 0; r < 8; r++) {
                float a = sA[ty * 8 + r][kc + k];
                acc[r][0] += a * w.x; acc[r][1] += a * w.y;
                acc[r][2] += a * w.z; acc[r][3] += a * w.w;
            }
        }
    }
    h4* out = (h4*)g_h1;
#pragma unroll
    for (int r = 0; r < 8; r++) {
        long rg = row0 + ty * 8 + r;
        if (rg < N_NODES) {
            h4 v;
            v.a = __floats2half2_rn(acc[r][0], acc[r][1]);
            v.b = __floats2half2_rn(acc[r][2], acc[r][3]);
            out[rg * 32 + tx] = v;
        }
    }
}

// ============ gather layer 1: agg(g_h1) -> +b1 -> BN -> ReLU -> g_h2 (fp16) ============
// warp per destination node; lane covers 4 columns (8 bytes)
__global__ void k_gather1(const float* __restrict__ b1, const float* __restrict__ gamma,
                          const float* __restrict__ beta) {
    int d = (int)((blockIdx.x * (long)blockDim.x + threadIdx.x) >> 5);
    int lane = threadIdx.x & 31;
    if (d >= N_NODES) return;
    int start = g_rowStart[d];
    int len   = g_deg[d] - 1;
    float dv  = g_dinv[d];
    const h4* in = (const h4*)g_h1;
    h4 self = in[(long)d * 32 + lane];
    float sc = dv * dv;
    float2 s0 = __half22float2(self.a), s1 = __half22float2(self.b);
    float ax = s0.x * sc, ay = s0.y * sc, az = s1.x * sc, aw = s1.y * sc;

    int j = 0;
    for (; j + 4 <= len; j += 4) {
        int2 e0 = g_epack[start + j],     e1 = g_epack[start + j + 1];
        int2 e2 = g_epack[start + j + 2], e3 = g_epack[start + j + 3];
        h4 v0 = in[(long)e0.x * 32 + lane];
        h4 v1 = in[(long)e1.x * 32 + lane];
        h4 v2 = in[(long)e2.x * 32 + lane];
        h4 v3 = in[(long)e3.x * 32 + lane];
        float n0 = __int_as_float(e0.y), n1 = __int_as_float(e1.y);
        float n2 = __int_as_float(e2.y), n3 = __int_as_float(e3.y);
        float2 a0 = __half22float2(v0.a), b0 = __half22float2(v0.b);
        float2 a1 = __half22float2(v1.a), b1v = __half22float2(v1.b);
        float2 a2 = __half22float2(v2.a), b2v = __half22float2(v2.b);
        float2 a3 = __half22float2(v3.a), b3v = __half22float2(v3.b);
        ax += n0 * a0.x + n1 * a1.x + n2 * a2.x + n3 * a3.x;
        ay += n0 * a0.y + n1 * a1.y + n2 * a2.y + n3 * a3.y;
        az += n0 * b0.x + n1 * b1v.x + n2 * b2v.x + n3 * b3v.x;
        aw += n0 * b0.y + n1 * b1v.y + n2 * b2v.y + n3 * b3v.y;
    }
    for (; j < len; j++) {
        int2 e = g_epack[start + j];
        float n = __int_as_float(e.y);
        h4 v = in[(long)e.x * 32 + lane];
        float2 a = __half22float2(v.a), b = __half22float2(v.b);
        ax += n * a.x; ay += n * a.y; az += n * b.x; aw += n * b.y;
    }

    int c4 = lane * 4;
    float4 bb = *(const float4*)&b1[c4];
    float4 gg = *(const float4*)&gamma[c4];
    float4 be = *(const float4*)&beta[c4];
    float inv = rsqrtf(1.0f + 1e-5f);
    float ox = fmaxf((ax + bb.x) * (gg.x * inv) + be.x, 0.f);
    float oy = fmaxf((ay + bb.y) * (gg.y * inv) + be.y, 0.f);
    float oz = fmaxf((az + bb.z) * (gg.z * inv) + be.z, 0.f);
    float ow = fmaxf((aw + bb.w) * (gg.w * inv) + be.w, 0.f);
    h4 o;
    o.a = __floats2half2_rn(ox, oy);
    o.b = __floats2half2_rn(oz, ow);
    ((h4*)g_h2)[(long)d * 32 + lane] = o;
}

// ===== gather layer 2: u[n] = (A_hat H)[n]; atomic pool into g_sums[batch[n]] =====
__global__ void k_gather2(const int* __restrict__ batch) {
    int d = (int)((blockIdx.x * (long)blockDim.x + threadIdx.x) >> 5);
    int lane = threadIdx.x & 31;
    if (d >= N_NODES) return;
    int start = g_rowStart[d];
    int len   = g_deg[d] - 1;
    float dv  = g_dinv[d];
    const h4* in = (const h4*)g_h2;
    h4 self = in[(long)d * 32 + lane];
    float sc = dv * dv;
    float2 s0 = __half22float2(self.a), s1 = __half22float2(self.b);
    float ax = s0.x * sc, ay = s0.y * sc, az = s1.x * sc, aw = s1.y * sc;

    int j = 0;
    for (; j + 4 <= len; j += 4) {
        int2 e0 = g_epack[start + j],     e1 = g_epack[start + j + 1];
        int2 e2 = g_epack[start + j + 2], e3 = g_epack[start + j + 3];
        h4 v0 = in[(long)e0.x * 32 + lane];
        h4 v1 = in[(long)e1.x * 32 + lane];
        h4 v2 = in[(long)e2.x * 32 + lane];
        h4 v3 = in[(long)e3.x * 32 + lane];
        float n0 = __int_as_float(e0.y), n1 = __int_as_float(e1.y);
        float n2 = __int_as_float(e2.y), n3 = __int_as_float(e3.y);
        float2 a0 = __half22float2(v0.a), b0 = __half22float2(v0.b);
        float2 a1 = __half22float2(v1.a), b1v = __half22float2(v1.b);
        float2 a2 = __half22float2(v2.a), b2v = __half22float2(v2.b);
        float2 a3 = __half22float2(v3.a), b3v = __half22float2(v3.b);
        ax += n0 * a0.x + n1 * a1.x + n2 * a2.x + n3 * a3.x;
        ay += n0 * a0.y + n1 * a1.y + n2 * a2.y + n3 * a3.y;
        az += n0 * b0.x + n1 * b1v.x + n2 * b2v.x + n3 * b3v.x;
        aw += n0 * b0.y + n1 * b1v.y + n2 * b2v.y + n3 * b3v.y;
    }
    for (; j < len; j++) {
        int2 e = g_epack[start + j];
        float n = __int_as_float(e.y);
        h4 v = in[(long)e.x * 32 + lane];
        float2 a = __half22float2(v.a), b = __half22float2(v.b);
        ax += n * a.x; ay += n * a.y; az += n * b.x; aw += n * b.y;
    }

    int b = batch[d];
    float* sdst = &g_sums[b * NH + lane * 4];
    atomicAdd(sdst + 0, ax);
    atomicAdd(sdst + 1, ay);
    atomicAdd(sdst + 2, az);
    atomicAdd(sdst + 3, aw);
}

// ==== final: g = (P @ W2)/cnt + b2 ; out = log_softmax(g @ clsW + clsb) ====
// one block of 128 threads per graph
__global__ void k_final(const float* __restrict__ W2, const float* __restrict__ b2,
                        const float* __restrict__ clsW, const float* __restrict__ clsb,
                        float* __restrict__ out) {
    int gph = blockIdx.x;
    int t = threadIdx.x;
    __shared__ float sp[NH];   // pooled sums P row
    __shared__ float sg[NH];   // g row
    __shared__ float sl[N_CLASS];
    __shared__ float lse;
    float cnt = fmaxf((float)g_cnt[gph], 1.0f);
    sp[t] = g_sums[gph * NH + t];
    __syncthreads();
    float acc = 0.f;
#pragma unroll 8
    for (int k = 0; k < NH; k++) acc += sp[k] * W2[k * NH + t];
    float gv = acc / cnt + b2[t];
    sg[t] = gv;
    out[N_GRAPHS * N_CLASS + gph * NH + t] = gv;   // g output
    __syncthreads();
    if (t < N_CLASS) {
        float a2 = clsb[t];
        for (int k = 0; k < NH; k++) a2 += sg[k] * clsW[k * N_CLASS + t];
        sl[t] = a2;
    }
    __syncthreads();
    if (t == 0) {
        float m = sl[0];
        for (int i = 1; i < N_CLASS; i++) m = fmaxf(m, sl[i]);
        float s = 0.f;
        for (int i = 0; i < N_CLASS; i++) s += expf(sl[i] - m);
        lse = m + logf(s);
    }
    __syncthreads();
    if (t < N_CLASS) out[gph * N_CLASS + t] = sl[t] - lse;  // log_softmax
}

extern "C" void kernel_launch(void* const* d_in, const int* in_sizes, int n_in,
                              void* d_out, int out_size) {
    const float* x     = (const float*)d_in[0];
    const int*   ei    = (const int*)d_in[1];
    const int*   batch = (const int*)d_in[2];
    const float* W1    = (const float*)d_in[3];
    const float* b1    = (const float*)d_in[4];
    const float* gamma = (const float*)d_in[5];
    const float* beta  = (const float*)d_in[6];
    const float* W2    = (const float*)d_in[7];
    const float* b2    = (const float*)d_in[8];
    const float* clsW  = (const float*)d_in[9];
    const float* clsb  = (const float*)d_in[10];
    float* out = (float*)d_out;

    const int* srcp = ei;
    const int* dstp = ei + N_EDGES;

    const int TPB = 256;
    int nodeBlocks = (N_NODES + TPB - 1) / TPB;
    int edgeBlocks = (N_EDGES + TPB - 1) / TPB;
    int gemmBlocks = (N_NODES + GR - 1) / GR;
    int gatherBlocks = (int)(((long)N_NODES * 32 + TPB - 1) / TPB);

    // ---- CSR + norm setup ----
    k_init<<<nodeBlocks, TPB>>>();
    k_count<<<edgeBlocks, TPB>>>(dstp);
    k_dinv<<<nodeBlocks, TPB>>>(batch);
    k_scanA<<<SCAN_G, SCAN_B>>>();
    k_scanB<<<1, 1>>>();
    k_scanC<<<SCAN_G, SCAN_B>>>();
    k_fill<<<edgeBlocks, TPB>>>(srcp, dstp);

    // ---- layer 1 ----
    k_gemm1<<<gemmBlocks, 256>>>(x, W1);
    k_gather1<<<gatherBlocks, TPB>>>(b1, gamma, beta);

    // ---- layer 2 (GEMM deferred to after pooling) ----
    k_gather2<<<gatherBlocks, TPB>>>(batch);

    // ---- final: tiny GEMM + classifier ----
    k_final<<<N_GRAPHS, NH>>>(W2, b2, clsW, clsb, out);
}

// round 8
// speedup vs baseline: 3.8492x; 1.1423x over previous
#include <cuda_runtime.h>
#include <cuda_fp16.h>
#include <math.h>

#define N_NODES  100000
#define N_EDGES  1600000
#define NH       128
#define N_GRAPHS 512
#define N_CLASS  10
#define GR       64
#define SCAN_B   1024
#define SCAN_G   98

// -------- scratch (device globals; no allocation allowed) --------
__device__ __half g_h1[N_NODES * NH];   // XW1 in fp16
__device__ __half g_h2[N_NODES * NH];   // H (post BN/ReLU) in fp16
__device__ float g_dinv[N_NODES];
__device__ int   g_deg[N_NODES];        // 1 + in-degree
__device__ int   g_rowStart[N_NODES];
__device__ int   g_cursor[N_NODES];
__device__ int2  g_epack[N_EDGES];      // {src, norm} sorted by dst
__device__ int   g_bsum[128];
__device__ int   g_boff[128];
__device__ float g_sums[N_GRAPHS * NH];
__device__ int   g_cnt[N_GRAPHS];

// ================= setup =================
__global__ void k_init() {
    int i = blockIdx.x * blockDim.x + threadIdx.x;
    if (i < N_NODES) { g_deg[i] = 1; g_cursor[i] = 0; }
    if (i < N_GRAPHS * NH) g_sums[i] = 0.f;
    if (i < N_GRAPHS) g_cnt[i] = 0;
}

__global__ void k_count(const int* __restrict__ dst) {
    int e = blockIdx.x * blockDim.x + threadIdx.x;
    if (e < N_EDGES) atomicAdd(&g_deg[dst[e]], 1);
}

__global__ void k_dinv(const int* __restrict__ batch) {
    int i = blockIdx.x * blockDim.x + threadIdx.x;
    if (i < N_NODES) {
        g_dinv[i] = rsqrtf((float)g_deg[i]);
        atomicAdd(&g_cnt[batch[i]], 1);
    }
}

__global__ void k_scanA() {
    __shared__ int s[SCAN_B];
    int t = threadIdx.x;
    int i = blockIdx.x * SCAN_B + t;
    int v = (i < N_NODES) ? (g_deg[i] - 1) : 0;
    s[t] = v;
    __syncthreads();
    for (int off = 1; off < SCAN_B; off <<= 1) {
        int add = (t >= off) ? s[t - off] : 0;
        __syncthreads();
        s[t] += add;
        __syncthreads();
    }
    if (i < N_NODES) g_rowStart[i] = s[t] - v;
    if (t == SCAN_B - 1) g_bsum[blockIdx.x] = s[t];
}

__global__ void k_scanB() {
    int run = 0;
    for (int b = 0; b < SCAN_G; b++) { g_boff[b] = run; run += g_bsum[b]; }
}

__global__ void k_scanC() {
    int i = blockIdx.x * SCAN_B + threadIdx.x;
    if (i < N_NODES) g_rowStart[i] += g_boff[blockIdx.x];
}

__global__ void k_fill(const int* __restrict__ srcp, const int* __restrict__ dstp) {
    int e = blockIdx.x * blockDim.x + threadIdx.x;
    if (e < N_EDGES) {
        int s = srcp[e], d = dstp[e];
        int pos = g_rowStart[d] + atomicAdd(&g_cursor[d], 1);
        float nrm = g_dinv[s] * g_dinv[d];
        g_epack[pos] = make_int2(s, __float_as_int(nrm));
    }
}

// ============ GEMM1: g_h1 = x @ W1 (fp32 math, fp16 out) ============
__global__ void k_gemm1(const float* __restrict__ A, const float* __restrict__ W) {
    __shared__ float sA[GR][132];
    __shared__ float sW[32 * NH];
    int t  = threadIdx.x;
    int tx = t & 31;
    int ty = t >> 5;
    long row0 = (long)blockIdx.x * GR;

    const float4* A4 = (const float4*)A;
    for (int i = t; i < GR * 32; i += 256) {
        int r = i >> 5, c = i & 31;
        long rg = row0 + r; if (rg > N_NODES - 1) rg = N_NODES - 1;
        float4 v = A4[rg * 32 + c];
        *(float4*)&sA[r][c * 4] = v;
    }

    float acc[8][4];
#pragma unroll
    for (int r = 0; r < 8; r++)
#pragma unroll
        for (int c = 0; c < 4; c++) acc[r][c] = 0.f;

    const float4* W4 = (const float4*)W;
    for (int kc = 0; kc < NH; kc += 32) {
        __syncthreads();
        for (int i = t; i < 32 * 32; i += 256)
            ((float4*)sW)[i] = W4[kc * 32 + i];
        __syncthreads();
#pragma unroll
        for (int k = 0; k < 32; k++) {
            float4 w = ((float4*)sW)[k * 32 + tx];
#pragma unroll
            for (int r = 0; r < 8; r++) {
                float a = sA[ty * 8 + r][kc + k];
                acc[r][0] += a * w.x; acc[r][1] += a * w.y;
                acc[r][2] += a * w.z; acc[r][3] += a * w.w;
            }
        }
    }
    __half2* out = (__half2*)g_h1;
#pragma unroll
    for (int r = 0; r < 8; r++) {
        long rg = row0 + ty * 8 + r;
        if (rg < N_NODES) {
            __half2 p0 = __floats2half2_rn(acc[r][0], acc[r][1]);
            __half2 p1 = __floats2half2_rn(acc[r][2], acc[r][3]);
            out[rg * 64 + tx * 2]     = p0;
            out[rg * 64 + tx * 2 + 1] = p1;
        }
    }
}

// -------- helpers --------
__device__ __forceinline__ void acc8(float* acc, int4 raw, float n) {
    __half2* h = (__half2*)&raw;
#pragma unroll
    for (int k = 0; k < 4; k++) {
        float2 f = __half22float2(h[k]);
        acc[2 * k]     += n * f.x;
        acc[2 * k + 1] += n * f.y;
    }
}

// Aggregate one node's row into acc[8] (lane li of half `half`).
// Two half-warps: each half processes alternate edges with LDG.128.
__device__ __forceinline__ void gather_node(const int4* in4, int d, int half, int li,
                                            float* acc) {
    int start = g_rowStart[d];
    int len   = g_deg[d] - 1;
    float dv  = g_dinv[d];
    if (half == 0) {
        int4 raw = in4[(long)d * 16 + li];
        float sc = dv * dv;
        __half2* h = (__half2*)&raw;
#pragma unroll
        for (int k = 0; k < 4; k++) {
            float2 f = __half22float2(h[k]);
            acc[2 * k]     = sc * f.x;
            acc[2 * k + 1] = sc * f.y;
        }
    } else {
#pragma unroll
        for (int k = 0; k < 8; k++) acc[k] = 0.f;
    }
    int j = half;
    for (; j + 2 < len; j += 4) {
        int2 ea = g_epack[start + j];
        int2 eb = g_epack[start + j + 2];
        int4 ra = in4[(long)ea.x * 16 + li];
        int4 rb = in4[(long)eb.x * 16 + li];
        acc8(acc, ra, __int_as_float(ea.y));
        acc8(acc, rb, __int_as_float(eb.y));
    }
    for (; j < len; j += 2) {
        int2 e = g_epack[start + j];
        int4 r = in4[(long)e.x * 16 + li];
        acc8(acc, r, __int_as_float(e.y));
    }
#pragma unroll
    for (int k = 0; k < 8; k++)
        acc[k] += __shfl_down_sync(0xffffffffu, acc[k], 16);
}

// ============ gather layer 1: agg(g_h1) -> +b1 -> BN -> ReLU -> g_h2 ============
__global__ void k_gather1(const float* __restrict__ b1, const float* __restrict__ gamma,
                          const float* __restrict__ beta) {
    int d = blockIdx.x * 8 + (threadIdx.x >> 5);
    int lane = threadIdx.x & 31;
    int half = lane >> 4, li = lane & 15;
    if (d >= N_NODES) return;
    float acc[8];
    gather_node((const int4*)g_h1, d, half, li, acc);
    if (half == 0) {
        int c8 = li * 8;
        float inv = rsqrtf(1.0f + 1e-5f);
        __half out[8];
#pragma unroll
        for (int k = 0; k < 8; k++) {
            float v = (acc[k] + b1[c8 + k]) * (gamma[c8 + k] * inv) + beta[c8 + k];
            out[k] = __float2half_rn(fmaxf(v, 0.f));
        }
        ((int4*)g_h2)[(long)d * 16 + li] = *(int4*)out;
    }
}

// ===== gather layer 2: agg(g_h2) pooled into g_sums via smem staging =====
__global__ void k_gather2(const int* __restrict__ batch) {
    __shared__ float sbuf[4][NH];
    __shared__ int sbase;
    int t = threadIdx.x;
    int w = t >> 5, lane = t & 31;
    int half = lane >> 4, li = lane & 15;
    int nb = blockIdx.x * 32;
    if (t == 0) sbase = batch[nb < N_NODES ? nb : N_NODES - 1];
    for (int i = t; i < 4 * NH; i += 256) ((float*)sbuf)[i] = 0.f;
    __syncthreads();
    int base = sbase;
    const int4* in4 = (const int4*)g_h2;

    for (int i = 0; i < 4; i++) {
        int d = nb + w * 4 + i;
        if (d >= N_NODES) break;
        float acc[8];
        gather_node(in4, d, half, li, acc);
        if (half == 0) {
            int b = batch[d];
            int slot = b - base;
            int c8 = li * 8;
            if (slot >= 0 && slot < 4) {
#pragma unroll
                for (int k = 0; k < 8; k++) atomicAdd(&sbuf[slot][c8 + k], acc[k]);
            } else {
#pragma unroll
                for (int k = 0; k < 8; k++) atomicAdd(&g_sums[b * NH + c8 + k], acc[k]);
            }
        }
    }
    __syncthreads();
    for (int i = t; i < 4 * NH; i += 256) {
        float v = ((float*)sbuf)[i];
        int slot = i >> 7, c = i & 127;
        int b = base + slot;
        if (v != 0.f && b < N_GRAPHS) atomicAdd(&g_sums[b * NH + c], v);
    }
}

// ==== final: g = (P @ W2)/cnt + b2 ; out = log_softmax(g @ clsW + clsb) ====
__global__ void k_final(const float* __restrict__ W2, const float* __restrict__ b2,
                        const float* __restrict__ clsW, const float* __restrict__ clsb,
                        float* __restrict__ out) {
    int gph = blockIdx.x;
    int t = threadIdx.x;
    __shared__ float sp[NH];
    __shared__ float sg[NH];
    __shared__ float sl[N_CLASS];
    __shared__ float lse;
    float cnt = fmaxf((float)g_cnt[gph], 1.0f);
    sp[t] = g_sums[gph * NH + t];
    __syncthreads();
    float acc = 0.f;
#pragma unroll 8
    for (int k = 0; k < NH; k++) acc += sp[k] * W2[k * NH + t];
    float gv = acc / cnt + b2[t];
    sg[t] = gv;
    out[N_GRAPHS * N_CLASS + gph * NH + t] = gv;
    __syncthreads();
    if (t < N_CLASS) {
        float a2 = clsb[t];
        for (int k = 0; k < NH; k++) a2 += sg[k] * clsW[k * N_CLASS + t];
        sl[t] = a2;
    }
    __syncthreads();
    if (t == 0) {
        float m = sl[0];
        for (int i = 1; i < N_CLASS; i++) m = fmaxf(m, sl[i]);
        float s = 0.f;
        for (int i = 0; i < N_CLASS; i++) s += expf(sl[i] - m);
        lse = m + logf(s);
    }
    __syncthreads();
    if (t < N_CLASS) out[gph * N_CLASS + t] = sl[t] - lse;
}

extern "C" void kernel_launch(void* const* d_in, const int* in_sizes, int n_in,
                              void* d_out, int out_size) {
    const float* x     = (const float*)d_in[0];
    const int*   ei    = (const int*)d_in[1];
    const int*   batch = (const int*)d_in[2];
    const float* W1    = (const float*)d_in[3];
    const float* b1    = (const float*)d_in[4];
    const float* gamma = (const float*)d_in[5];
    const float* beta  = (const float*)d_in[6];
    const float* W2    = (const float*)d_in[7];
    const float* b2    = (const float*)d_in[8];
    const float* clsW  = (const float*)d_in[9];
    const float* clsb  = (const float*)d_in[10];
    float* out = (float*)d_out;

    const int* srcp = ei;
    const int* dstp = ei + N_EDGES;

    const int TPB = 256;
    int nodeBlocks = (N_NODES + TPB - 1) / TPB;
    int edgeBlocks = (N_EDGES + TPB - 1) / TPB;
    int gemmBlocks = (N_NODES + GR - 1) / GR;

    // ---- CSR + norm setup ----
    k_init<<<nodeBlocks, TPB>>>();
    k_count<<<edgeBlocks, TPB>>>(dstp);
    k_dinv<<<nodeBlocks, TPB>>>(batch);
    k_scanA<<<SCAN_G, SCAN_B>>>();
    k_scanB<<<1, 1>>>();
    k_scanC<<<SCAN_G, SCAN_B>>>();
    k_fill<<<edgeBlocks, TPB>>>(srcp, dstp);

    // ---- layer 1 ----
    k_gemm1<<<gemmBlocks, 256>>>(x, W1);
    k_gather1<<<(N_NODES + 7) / 8, 256>>>(b1, gamma, beta);

    // ---- layer 2 aggregation + pool (GEMM deferred) ----
    k_gather2<<<(N_NODES + 31) / 32, 256>>>(batch);

    // ---- final ----
    k_final<<<N_GRAPHS, NH>>>(W2, b2, clsW, clsb, out);
}

// round 9
// speedup vs baseline: 4.1999x; 1.0911x over previous
#include <cuda_runtime.h>
#include <cuda_fp16.h>
#include <mma.h>
#include <math.h>

using namespace nvcuda;

#define N_NODES  100000
#define N_EDGES  1600000
#define NH       128
#define N_GRAPHS 512
#define N_CLASS  10
#define SCAN_B   1024
#define SCAN_G   98

// -------- scratch (device globals; no allocation allowed) --------
__device__ __half g_h1[N_NODES * NH];   // XW1 in fp16
__device__ __half g_h2[N_NODES * NH];   // H (post BN/ReLU) in fp16
__device__ __half g_W1h[NH * NH];       // W1 in fp16
__device__ float g_dinv[N_NODES];
__device__ int   g_deg[N_NODES];        // 1 + in-degree
__device__ int   g_rowStart[N_NODES];
__device__ int   g_cursor[N_NODES];
__device__ int2  g_epack[N_EDGES];      // {src, norm} sorted by dst
__device__ int   g_bsum[128];
__device__ int   g_boff[128];
__device__ float g_sums[N_GRAPHS * NH];
__device__ int   g_cnt[N_GRAPHS];

// ================= setup =================
__global__ void k_init() {
    int i = blockIdx.x * blockDim.x + threadIdx.x;
    if (i < N_NODES) { g_deg[i] = 1; g_cursor[i] = 0; }
    if (i < N_GRAPHS * NH) g_sums[i] = 0.f;
    if (i < N_GRAPHS) g_cnt[i] = 0;
}

__global__ void k_count(const int* __restrict__ dst) {
    int e = blockIdx.x * blockDim.x + threadIdx.x;
    if (e < N_EDGES) atomicAdd(&g_deg[dst[e]], 1);
}

__global__ void k_dinv(const int* __restrict__ batch) {
    int i = blockIdx.x * blockDim.x + threadIdx.x;
    if (i < N_NODES) {
        g_dinv[i] = rsqrtf((float)g_deg[i]);
        atomicAdd(&g_cnt[batch[i]], 1);
    }
}

__global__ void k_scanA() {
    __shared__ int s[SCAN_B];
    int t = threadIdx.x;
    int i = blockIdx.x * SCAN_B + t;
    int v = (i < N_NODES) ? (g_deg[i] - 1) : 0;
    s[t] = v;
    __syncthreads();
    for (int off = 1; off < SCAN_B; off <<= 1) {
        int add = (t >= off) ? s[t - off] : 0;
        __syncthreads();
        s[t] += add;
        __syncthreads();
    }
    if (i < N_NODES) g_rowStart[i] = s[t] - v;
    if (t == SCAN_B - 1) g_bsum[blockIdx.x] = s[t];
}

__global__ void k_scanB() {
    int run = 0;
    for (int b = 0; b < SCAN_G; b++) { g_boff[b] = run; run += g_bsum[b]; }
}

__global__ void k_scanC() {
    int i = blockIdx.x * SCAN_B + threadIdx.x;
    if (i < N_NODES) g_rowStart[i] += g_boff[blockIdx.x];
}

__global__ void k_fill(const int* __restrict__ srcp, const int* __restrict__ dstp) {
    int e = blockIdx.x * blockDim.x + threadIdx.x;
    if (e < N_EDGES) {
        int s = srcp[e], d = dstp[e];
        int pos = g_rowStart[d] + atomicAdd(&g_cursor[d], 1);
        float nrm = g_dinv[s] * g_dinv[d];
        g_epack[pos] = make_int2(s, __float_as_int(nrm));
    }
}

// ============ W1 fp32 -> fp16 ============
__global__ void k_wconv(const float* __restrict__ W) {
    int i = blockIdx.x * blockDim.x + threadIdx.x;
    if (i < NH * NH) g_W1h[i] = __float2half_rn(W[i]);
}

// ============ GEMM1 (tensor cores): g_h1 = fp16(x) @ fp16(W1), fp32 accum ============
// block = 128 threads (4 warps), 64 rows/block; each warp: 16 rows x 128 cols
__global__ void k_gemmT(const float* __restrict__ A) {
    __shared__ __align__(16) char smemraw[49152];
    __half* sA = (__half*)smemraw;             // 64 x 128 fp16 = 16KB
    __half* sW = (__half*)(smemraw + 16384);   // 128 x 128 fp16 = 32KB
    float*  sC = (float*)smemraw;              // 64 x 128 f32 (epilogue reuse)
    int t = threadIdx.x;
    int w = t >> 5;
    long row0 = (long)blockIdx.x * 64;

    // stage W (pre-converted fp16)
    const int4* Wh4 = (const int4*)g_W1h;
    int4* sW4 = (int4*)sW;
    for (int i = t; i < 2048; i += 128) sW4[i] = Wh4[i];

    // stage A tile, converting fp32 -> fp16
    const float4* A4 = (const float4*)A;
    __half2* sA2 = (__half2*)sA;
    for (int i = t; i < 2048; i += 128) {
        int r = i >> 5, c = i & 31;
        long rg = row0 + r; if (rg >= N_NODES) rg = N_NODES - 1;
        float4 v = A4[rg * 32 + c];
        sA2[r * 64 + c * 2]     = __floats2half2_rn(v.x, v.y);
        sA2[r * 64 + c * 2 + 1] = __floats2half2_rn(v.z, v.w);
    }
    __syncthreads();

    wmma::fragment<wmma::accumulator, 16, 16, 16, float> cf[8];
#pragma unroll
    for (int n = 0; n < 8; n++) wmma::fill_fragment(cf[n], 0.f);
#pragma unroll
    for (int k0 = 0; k0 < 8; k0++) {
        wmma::fragment<wmma::matrix_a, 16, 16, 16, __half, wmma::row_major> af;
        wmma::load_matrix_sync(af, sA + (w * 16) * 128 + k0 * 16, 128);
#pragma unroll
        for (int n = 0; n < 8; n++) {
            wmma::fragment<wmma::matrix_b, 16, 16, 16, __half, wmma::row_major> bf;
            wmma::load_matrix_sync(bf, sW + (k0 * 16) * 128 + n * 16, 128);
            wmma::mma_sync(cf[n], af, bf, cf[n]);
        }
    }
    __syncthreads();   // done reading sA/sW; reuse as sC
#pragma unroll
    for (int n = 0; n < 8; n++)
        wmma::store_matrix_sync(sC + (w * 16) * 128 + n * 16, cf[n], 128, wmma::mem_row_major);
    __syncthreads();

    __half2* out2 = (__half2*)g_h1;
    const float2* sC2 = (const float2*)sC;
    for (int i = t; i < 64 * 64; i += 128) {
        int r = i >> 6, c = i & 63;
        long rg = row0 + r;
        if (rg < N_NODES) {
            float2 v = sC2[r * 64 + c];
            out2[rg * 64 + c] = __floats2half2_rn(v.x, v.y);
        }
    }
}

// -------- gather helpers --------
__device__ __forceinline__ void acc8(float* acc, int4 raw, float n) {
    __half2* h = (__half2*)&raw;
#pragma unroll
    for (int k = 0; k < 4; k++) {
        float2 f = __half22float2(h[k]);
        acc[2 * k]     += n * f.x;
        acc[2 * k + 1] += n * f.y;
    }
}

// Aggregate one node's row into acc[8] (lane li of half `half`).
__device__ __forceinline__ void gather_node(const int4* in4, int d, int half, int li,
                                            float* acc) {
    int start = g_rowStart[d];
    int len   = g_deg[d] - 1;
    float dv  = g_dinv[d];
    if (half == 0) {
        int4 raw = in4[(long)d * 16 + li];
        float sc = dv * dv;
        __half2* h = (__half2*)&raw;
#pragma unroll
        for (int k = 0; k < 4; k++) {
            float2 f = __half22float2(h[k]);
            acc[2 * k]     = sc * f.x;
            acc[2 * k + 1] = sc * f.y;
        }
    } else {
#pragma unroll
        for (int k = 0; k < 8; k++) acc[k] = 0.f;
    }
    int j = half;
    for (; j + 2 < len; j += 4) {
        int2 ea = g_epack[start + j];
        int2 eb = g_epack[start + j + 2];
        int4 ra = in4[(long)ea.x * 16 + li];
        int4 rb = in4[(long)eb.x * 16 + li];
        acc8(acc, ra, __int_as_float(ea.y));
        acc8(acc, rb, __int_as_float(eb.y));
    }
    for (; j < len; j += 2) {
        int2 e = g_epack[start + j];
        int4 r = in4[(long)e.x * 16 + li];
        acc8(acc, r, __int_as_float(e.y));
    }
#pragma unroll
    for (int k = 0; k < 8; k++)
        acc[k] += __shfl_down_sync(0xffffffffu, acc[k], 16);
}

// ============ gather layer 1: agg(g_h1) -> +b1 -> BN -> ReLU -> g_h2 ============
__global__ void k_gather1(const float* __restrict__ b1, const float* __restrict__ gamma,
                          const float* __restrict__ beta) {
    int d = blockIdx.x * 8 + (threadIdx.x >> 5);
    int lane = threadIdx.x & 31;
    int half = lane >> 4, li = lane & 15;
    if (d >= N_NODES) return;
    float acc[8];
    gather_node((const int4*)g_h1, d, half, li, acc);
    if (half == 0) {
        int c8 = li * 8;
        float inv = rsqrtf(1.0f + 1e-5f);
        __half out[8];
#pragma unroll
        for (int k = 0; k < 8; k++) {
            float v = (acc[k] + b1[c8 + k]) * (gamma[c8 + k] * inv) + beta[c8 + k];
            out[k] = __float2half_rn(fmaxf(v, 0.f));
        }
        ((int4*)g_h2)[(long)d * 16 + li] = *(int4*)out;
    }
}

// ===== gather layer 2: agg(g_h2) pooled into g_sums via smem staging =====
__global__ void k_gather2(const int* __restrict__ batch) {
    __shared__ float sbuf[4][NH];
    __shared__ int sbase;
    int t = threadIdx.x;
    int w = t >> 5, lane = t & 31;
    int half = lane >> 4, li = lane & 15;
    int nb = blockIdx.x * 32;
    if (t == 0) sbase = batch[nb < N_NODES ? nb : N_NODES - 1];
    for (int i = t; i < 4 * NH; i += 256) ((float*)sbuf)[i] = 0.f;
    __syncthreads();
    int base = sbase;
    const int4* in4 = (const int4*)g_h2;

    for (int i = 0; i < 4; i++) {
        int d = nb + w * 4 + i;
        if (d >= N_NODES) break;
        float acc[8];
        gather_node(in4, d, half, li, acc);
        if (half == 0) {
            int b = batch[d];
            int slot = b - base;
            int c8 = li * 8;
            if (slot >= 0 && slot < 4) {
#pragma unroll
                for (int k = 0; k < 8; k++) atomicAdd(&sbuf[slot][c8 + k], acc[k]);
            } else {
#pragma unroll
                for (int k = 0; k < 8; k++) atomicAdd(&g_sums[b * NH + c8 + k], acc[k]);
            }
        }
    }
    __syncthreads();
    for (int i = t; i < 4 * NH; i += 256) {
        float v = ((float*)sbuf)[i];
        int slot = i >> 7, c = i & 127;
        int b = base + slot;
        if (v != 0.f && b < N_GRAPHS) atomicAdd(&g_sums[b * NH + c], v);
    }
}

// ==== final: g = (P @ W2)/cnt + b2 ; out = log_softmax(g @ clsW + clsb) ====
__global__ void k_final(const float* __restrict__ W2, const float* __restrict__ b2,
                        const float* __restrict__ clsW, const float* __restrict__ clsb,
                        float* __restrict__ out) {
    int gph = blockIdx.x;
    int t = threadIdx.x;
    __shared__ float sp[NH];
    __shared__ float sg[NH];
    __shared__ float sl[N_CLASS];
    __shared__ float lse;
    float cnt = fmaxf((float)g_cnt[gph], 1.0f);
    sp[t] = g_sums[gph * NH + t];
    __syncthreads();
    float acc = 0.f;
#pragma unroll 8
    for (int k = 0; k < NH; k++) acc += sp[k] * W2[k * NH + t];
    float gv = acc / cnt + b2[t];
    sg[t] = gv;
    out[N_GRAPHS * N_CLASS + gph * NH + t] = gv;
    __syncthreads();
    if (t < N_CLASS) {
        float a2 = clsb[t];
        for (int k = 0; k < NH; k++) a2 += sg[k] * clsW[k * N_CLASS + t];
        sl[t] = a2;
    }
    __syncthreads();
    if (t == 0) {
        float m = sl[0];
        for (int i = 1; i < N_CLASS; i++) m = fmaxf(m, sl[i]);
        float s = 0.f;
        for (int i = 0; i < N_CLASS; i++) s += expf(sl[i] - m);
        lse = m + logf(s);
    }
    __syncthreads();
    if (t < N_CLASS) out[gph * N_CLASS + t] = sl[t] - lse;
}

extern "C" void kernel_launch(void* const* d_in, const int* in_sizes, int n_in,
                              void* d_out, int out_size) {
    const float* x     = (const float*)d_in[0];
    const int*   ei    = (const int*)d_in[1];
    const int*   batch = (const int*)d_in[2];
    const float* W1    = (const float*)d_in[3];
    const float* b1    = (const float*)d_in[4];
    const float* gamma = (const float*)d_in[5];
    const float* beta  = (const float*)d_in[6];
    const float* W2    = (const float*)d_in[7];
    const float* b2    = (const float*)d_in[8];
    const float* clsW  = (const float*)d_in[9];
    const float* clsb  = (const float*)d_in[10];
    float* out = (float*)d_out;

    const int* srcp = ei;
    const int* dstp = ei + N_EDGES;

    const int TPB = 256;
    int nodeBlocks = (N_NODES + TPB - 1) / TPB;
    int edgeBlocks = (N_EDGES + TPB - 1) / TPB;

    // created once per process (host-side resources only); reused across calls
    static cudaStream_t s1 = []() {
        cudaStream_t s; cudaStreamCreateWithFlags(&s, cudaStreamNonBlocking); return s;
    }();
    static cudaEvent_t evRoot = []() {
        cudaEvent_t e; cudaEventCreateWithFlags(&e, cudaEventDisableTiming); return e;
    }();
    static cudaEvent_t evSetup = []() {
        cudaEvent_t e; cudaEventCreateWithFlags(&e, cudaEventDisableTiming); return e;
    }();

    // fork: CSR/norm setup chain on s1
    cudaEventRecord(evRoot, 0);
    cudaStreamWaitEvent(s1, evRoot, 0);
    k_init<<<nodeBlocks, TPB, 0, s1>>>();
    k_count<<<edgeBlocks, TPB, 0, s1>>>(dstp);
    k_dinv<<<nodeBlocks, TPB, 0, s1>>>(batch);
    k_scanA<<<SCAN_G, SCAN_B, 0, s1>>>();
    k_scanB<<<1, 1, 0, s1>>>();
    k_scanC<<<SCAN_G, SCAN_B, 0, s1>>>();
    k_fill<<<edgeBlocks, TPB, 0, s1>>>(srcp, dstp);
    cudaEventRecord(evSetup, s1);

    // main stream: tensor-core GEMM1 (independent of setup)
    k_wconv<<<64, 256>>>(W1);
    k_gemmT<<<(N_NODES + 63) / 64, 128>>>(x);

    // join, then gathers + final
    cudaStreamWaitEvent(0, evSetup, 0);
    k_gather1<<<(N_NODES + 7) / 8, 256>>>(b1, gamma, beta);
    k_gather2<<<(N_NODES + 31) / 32, 256>>>(batch);
    k_final<<<N_GRAPHS, NH>>>(W2, b2, clsW, clsb, out);
}

// round 10
// speedup vs baseline: 4.4276x; 1.0542x over previous
#include <cuda_runtime.h>
#include <cuda_fp16.h>
#include <mma.h>
#include <math.h>

using namespace nvcuda;

#define N_NODES  100000
#define N_EDGES  1600000
#define NH       128
#define N_GRAPHS 512
#define N_CLASS  10
#define SCAN_B   1024
#define SCAN_G   98

// -------- scratch (device globals; no allocation allowed) --------
__device__ __half g_h1[N_NODES * NH];   // XW1 in fp16
__device__ __half g_h2[N_NODES * NH];   // H (post BN/ReLU) in fp16
__device__ __half g_W1h[NH * NH];       // W1 in fp16
__device__ float g_bnA[NH];             // gamma / sqrt(1+eps)
__device__ float g_bnB[NH];             // b1*bnA + beta
__device__ float g_dinv[N_NODES];
__device__ int   g_deg[N_NODES];        // 1 + in-degree
__device__ int   g_rowStart[N_NODES];
__device__ int   g_cursor[N_NODES];     // pre-init to rowStart
__device__ int2  g_epack[N_EDGES];      // {src, norm} sorted by dst
__device__ int   g_bsum[128];
__device__ int   g_boff[128];
__device__ float g_sums[N_GRAPHS * NH];
__device__ int   g_cnt[N_GRAPHS];

// ================= setup =================
__global__ void k_init() {
    int i = blockIdx.x * blockDim.x + threadIdx.x;
    if (i < N_NODES) g_deg[i] = 1;
    if (i < N_GRAPHS * NH) g_sums[i] = 0.f;
    if (i < N_GRAPHS) g_cnt[i] = 0;
}

__global__ void k_count(const int* __restrict__ dst) {
    int e = blockIdx.x * blockDim.x + threadIdx.x;
    if (e < N_EDGES) atomicAdd(&g_deg[dst[e]], 1);
}

__global__ void k_dinv(const int* __restrict__ batch) {
    int i = blockIdx.x * blockDim.x + threadIdx.x;
    if (i < N_NODES) {
        g_dinv[i] = rsqrtf((float)g_deg[i]);
        atomicAdd(&g_cnt[batch[i]], 1);
    }
}

__global__ void k_scanA() {
    __shared__ int s[SCAN_B];
    int t = threadIdx.x;
    int i = blockIdx.x * SCAN_B + t;
    int v = (i < N_NODES) ? (g_deg[i] - 1) : 0;
    s[t] = v;
    __syncthreads();
    for (int off = 1; off < SCAN_B; off <<= 1) {
        int add = (t >= off) ? s[t - off] : 0;
        __syncthreads();
        s[t] += add;
        __syncthreads();
    }
    if (i < N_NODES) g_rowStart[i] = s[t] - v;
    if (t == SCAN_B - 1) g_bsum[blockIdx.x] = s[t];
}

__global__ void k_scanB() {
    int run = 0;
    for (int b = 0; b < SCAN_G; b++) { g_boff[b] = run; run += g_bsum[b]; }
}

__global__ void k_scanC() {
    int i = blockIdx.x * SCAN_B + threadIdx.x;
    if (i < N_NODES) {
        int rs = g_rowStart[i] + g_boff[blockIdx.x];
        g_rowStart[i] = rs;
        g_cursor[i]   = rs;     // cursor starts at row base: fill does 1 atomic only
    }
}

__global__ void k_fill(const int* __restrict__ srcp, const int* __restrict__ dstp) {
    int e = blockIdx.x * blockDim.x + threadIdx.x;
    if (e < N_EDGES) {
        int s = srcp[e], d = dstp[e];
        int pos = atomicAdd(&g_cursor[d], 1);
        float nrm = g_dinv[s] * g_dinv[d];
        g_epack[pos] = make_int2(s, __float_as_int(nrm));
    }
}

// ============ W1 fp32 -> fp16, plus BN constant prep ============
__global__ void k_wconv(const float* __restrict__ W, const float* __restrict__ b1,
                        const float* __restrict__ gamma, const float* __restrict__ beta) {
    int i = blockIdx.x * blockDim.x + threadIdx.x;
    if (i < NH * NH) g_W1h[i] = __float2half_rn(W[i]);
    if (i < NH) {
        float a = gamma[i] * rsqrtf(1.0f + 1e-5f);
        g_bnA[i] = a;
        g_bnB[i] = b1[i] * a + beta[i];
    }
}

// ============ GEMM1 (tensor cores): g_h1 = fp16(x) @ fp16(W1), fp32 accum ============
__global__ void k_gemmT(const float* __restrict__ A) {
    __shared__ __align__(16) char smemraw[49152];
    __half* sA = (__half*)smemraw;             // 64 x 128 fp16
    __half* sW = (__half*)(smemraw + 16384);   // 128 x 128 fp16
    float*  sC = (float*)smemraw;              // epilogue reuse
    int t = threadIdx.x;
    int w = t >> 5;
    long row0 = (long)blockIdx.x * 64;

    const int4* Wh4 = (const int4*)g_W1h;
    int4* sW4 = (int4*)sW;
    for (int i = t; i < 2048; i += 128) sW4[i] = Wh4[i];

    const float4* A4 = (const float4*)A;
    __half2* sA2 = (__half2*)sA;
    for (int i = t; i < 2048; i += 128) {
        int r = i >> 5, c = i & 31;
        long rg = row0 + r; if (rg >= N_NODES) rg = N_NODES - 1;
        float4 v = A4[rg * 32 + c];
        sA2[r * 64 + c * 2]     = __floats2half2_rn(v.x, v.y);
        sA2[r * 64 + c * 2 + 1] = __floats2half2_rn(v.z, v.w);
    }
    __syncthreads();

    wmma::fragment<wmma::accumulator, 16, 16, 16, float> cf[8];
#pragma unroll
    for (int n = 0; n < 8; n++) wmma::fill_fragment(cf[n], 0.f);
#pragma unroll
    for (int k0 = 0; k0 < 8; k0++) {
        wmma::fragment<wmma::matrix_a, 16, 16, 16, __half, wmma::row_major> af;
        wmma::load_matrix_sync(af, sA + (w * 16) * 128 + k0 * 16, 128);
#pragma unroll
        for (int n = 0; n < 8; n++) {
            wmma::fragment<wmma::matrix_b, 16, 16, 16, __half, wmma::row_major> bf;
            wmma::load_matrix_sync(bf, sW + (k0 * 16) * 128 + n * 16, 128);
            wmma::mma_sync(cf[n], af, bf, cf[n]);
        }
    }
    __syncthreads();
#pragma unroll
    for (int n = 0; n < 8; n++)
        wmma::store_matrix_sync(sC + (w * 16) * 128 + n * 16, cf[n], 128, wmma::mem_row_major);
    __syncthreads();

    __half2* out2 = (__half2*)g_h1;
    const float2* sC2 = (const float2*)sC;
    for (int i = t; i < 64 * 64; i += 128) {
        int r = i >> 6, c = i & 63;
        long rg = row0 + r;
        if (rg < N_NODES) {
            float2 v = sC2[r * 64 + c];
            out2[rg * 64 + c] = __floats2half2_rn(v.x, v.y);
        }
    }
}

// -------- gather helpers --------
__device__ __forceinline__ void acc8(float* acc, int4 raw, float n) {
    __half2* h = (__half2*)&raw;
#pragma unroll
    for (int k = 0; k < 4; k++) {
        float2 f = __half22float2(h[k]);
        acc[2 * k]     += n * f.x;
        acc[2 * k + 1] += n * f.y;
    }
}

// Aggregate node d's row into acc[8]; two half-warps alternate edges.
// Unroll 4 per half: 4 independent LDG.128 in flight per half-warp.
__device__ __forceinline__ void gather_node(const int4* in4, int d, int half, int li,
                                            float* acc) {
    int start = g_rowStart[d];
    int len   = g_deg[d] - 1;
    float dv  = g_dinv[d];
    if (half == 0) {
        int4 raw = in4[(long)d * 16 + li];
        float sc = dv * dv;
        __half2* h = (__half2*)&raw;
#pragma unroll
        for (int k = 0; k < 4; k++) {
            float2 f = __half22float2(h[k]);
            acc[2 * k]     = sc * f.x;
            acc[2 * k + 1] = sc * f.y;
        }
    } else {
#pragma unroll
        for (int k = 0; k < 8; k++) acc[k] = 0.f;
    }
    const int2* ep = g_epack + start;
    int j = half;
    for (; j + 6 < len; j += 8) {
        int2 e0 = ep[j],     e1 = ep[j + 2];
        int2 e2 = ep[j + 4], e3 = ep[j + 6];
        int4 r0 = in4[(long)e0.x * 16 + li];
        int4 r1 = in4[(long)e1.x * 16 + li];
        int4 r2 = in4[(long)e2.x * 16 + li];
        int4 r3 = in4[(long)e3.x * 16 + li];
        acc8(acc, r0, __int_as_float(e0.y));
        acc8(acc, r1, __int_as_float(e1.y));
        acc8(acc, r2, __int_as_float(e2.y));
        acc8(acc, r3, __int_as_float(e3.y));
    }
    for (; j < len; j += 2) {
        int2 e = ep[j];
        int4 r = in4[(long)e.x * 16 + li];
        acc8(acc, r, __int_as_float(e.y));
    }
#pragma unroll
    for (int k = 0; k < 8; k++)
        acc[k] += __shfl_down_sync(0xffffffffu, acc[k], 16);
}

// ============ gather layer 1: agg(g_h1) -> BN(+b1) -> ReLU -> g_h2 ============
__global__ void __launch_bounds__(256, 4)
k_gather1() {
    int d = blockIdx.x * 8 + (threadIdx.x >> 5);
    int lane = threadIdx.x & 31;
    int half = lane >> 4, li = lane & 15;
    if (d >= N_NODES) return;
    float acc[8];
    gather_node((const int4*)g_h1, d, half, li, acc);
    if (half == 0) {
        int c8 = li * 8;
        float4 A0 = *(const float4*)&g_bnA[c8], A1 = *(const float4*)&g_bnA[c8 + 4];
        float4 B0 = *(const float4*)&g_bnB[c8], B1 = *(const float4*)&g_bnB[c8 + 4];
        const float* Ap = &A0.x; const float* Bp = &B0.x;
        float Aa[8] = {A0.x, A0.y, A0.z, A0.w, A1.x, A1.y, A1.z, A1.w};
        float Bb[8] = {B0.x, B0.y, B0.z, B0.w, B1.x, B1.y, B1.z, B1.w};
        (void)Ap; (void)Bp;
        __half out[8];
#pragma unroll
        for (int k = 0; k < 8; k++)
            out[k] = __float2half_rn(fmaxf(acc[k] * Aa[k] + Bb[k], 0.f));
        ((int4*)g_h2)[(long)d * 16 + li] = *(int4*)out;
    }
}

// ===== gather layer 2: agg(g_h2) pooled into g_sums via smem staging =====
__global__ void __launch_bounds__(256, 4)
k_gather2(const int* __restrict__ batch) {
    __shared__ float sbuf[4][NH];
    __shared__ int sbase;
    int t = threadIdx.x;
    int w = t >> 5, lane = t & 31;
    int half = lane >> 4, li = lane & 15;
    int nb = blockIdx.x * 32;
    if (t == 0) sbase = batch[nb < N_NODES ? nb : N_NODES - 1];
    for (int i = t; i < 4 * NH; i += 256) ((float*)sbuf)[i] = 0.f;
    __syncthreads();
    int base = sbase;
    const int4* in4 = (const int4*)g_h2;

    for (int i = 0; i < 4; i++) {
        int d = nb + w * 4 + i;
        if (d >= N_NODES) break;
        float acc[8];
        gather_node(in4, d, half, li, acc);
        if (half == 0) {
            int b = batch[d];
            int slot = b - base;
            int c8 = li * 8;
            if (slot >= 0 && slot < 4) {
#pragma unroll
                for (int k = 0; k < 8; k++) atomicAdd(&sbuf[slot][c8 + k], acc[k]);
            } else {
#pragma unroll
                for (int k = 0; k < 8; k++) atomicAdd(&g_sums[b * NH + c8 + k], acc[k]);
            }
        }
    }
    __syncthreads();
    for (int i = t; i < 4 * NH; i += 256) {
        float v = ((float*)sbuf)[i];
        int slot = i >> 7, c = i & 127;
        int b = base + slot;
        if (v != 0.f && b < N_GRAPHS) atomicAdd(&g_sums[b * NH + c], v);
    }
}

// ==== final: g = (P @ W2)/cnt + b2 ; out = log_softmax(g @ clsW + clsb) ====
__global__ void k_final(const float* __restrict__ W2, const float* __restrict__ b2,
                        const float* __restrict__ clsW, const float* __restrict__ clsb,
                        float* __restrict__ out) {
    int gph = blockIdx.x;
    int t = threadIdx.x;
    __shared__ float sp[NH];
    __shared__ float sg[NH];
    __shared__ float sl[N_CLASS];
    __shared__ float lse;
    float cnt = fmaxf((float)g_cnt[gph], 1.0f);
    sp[t] = g_sums[gph * NH + t];
    __syncthreads();
    float acc = 0.f;
#pragma unroll 8
    for (int k = 0; k < NH; k++) acc += sp[k] * W2[k * NH + t];
    float gv = acc / cnt + b2[t];
    sg[t] = gv;
    out[N_GRAPHS * N_CLASS + gph * NH + t] = gv;
    __syncthreads();
    if (t < N_CLASS) {
        float a2 = clsb[t];
        for (int k = 0; k < NH; k++) a2 += sg[k] * clsW[k * N_CLASS + t];
        sl[t] = a2;
    }
    __syncthreads();
    if (t == 0) {
        float m = sl[0];
        for (int i = 1; i < N_CLASS; i++) m = fmaxf(m, sl[i]);
        float s = 0.f;
        for (int i = 0; i < N_CLASS; i++) s += expf(sl[i] - m);
        lse = m + logf(s);
    }
    __syncthreads();
    if (t < N_CLASS) out[gph * N_CLASS + t] = sl[t] - lse;
}

extern "C" void kernel_launch(void* const* d_in, const int* in_sizes, int n_in,
                              void* d_out, int out_size) {
    const float* x     = (const float*)d_in[0];
    const int*   ei    = (const int*)d_in[1];
    const int*   batch = (const int*)d_in[2];
    const float* W1    = (const float*)d_in[3];
    const float* b1    = (const float*)d_in[4];
    const float* gamma = (const float*)d_in[5];
    const float* beta  = (const float*)d_in[6];
    const float* W2    = (const float*)d_in[7];
    const float* b2    = (const float*)d_in[8];
    const float* clsW  = (const float*)d_in[9];
    const float* clsb  = (const float*)d_in[10];
    float* out = (float*)d_out;

    const int* srcp = ei;
    const int* dstp = ei + N_EDGES;

    const int TPB = 256;
    int nodeBlocks = (N_NODES + TPB - 1) / TPB;
    int edgeBlocks = (N_EDGES + TPB - 1) / TPB;

    static cudaStream_t s1 = []() {
        cudaStream_t s; cudaStreamCreateWithFlags(&s, cudaStreamNonBlocking); return s;
    }();
    static cudaEvent_t evRoot = []() {
        cudaEvent_t e; cudaEventCreateWithFlags(&e, cudaEventDisableTiming); return e;
    }();
    static cudaEvent_t evSetup = []() {
        cudaEvent_t e; cudaEventCreateWithFlags(&e, cudaEventDisableTiming); return e;
    }();

    // fork: CSR/norm setup chain on s1
    cudaEventRecord(evRoot, 0);
    cudaStreamWaitEvent(s1, evRoot, 0);
    k_init<<<nodeBlocks, TPB, 0, s1>>>();
    k_count<<<edgeBlocks, TPB, 0, s1>>>(dstp);
    k_dinv<<<nodeBlocks, TPB, 0, s1>>>(batch);
    k_scanA<<<SCAN_G, SCAN_B, 0, s1>>>();
    k_scanB<<<1, 1, 0, s1>>>();
    k_scanC<<<SCAN_G, SCAN_B, 0, s1>>>();
    k_fill<<<edgeBlocks, TPB, 0, s1>>>(srcp, dstp);
    cudaEventRecord(evSetup, s1);

    // main stream: tensor-core GEMM1 (independent of setup)
    k_wconv<<<64, 256>>>(W1, b1, gamma, beta);
    k_gemmT<<<(N_NODES + 63) / 64, 128>>>(x);

    // join, then gathers + final
    cudaStreamWaitEvent(0, evSetup, 0);
    k_gather1<<<(N_NODES + 7) / 8, 256>>>();
    k_gather2<<<(N_NODES + 31) / 32, 256>>>(batch);
    k_final<<<N_GRAPHS, NH>>>(W2, b2, clsW, clsb, out);
}

// round 11
// speedup vs baseline: 4.6282x; 1.0453x over previous
#include <cuda_runtime.h>
#include <cuda_bf16.h>
#include <mma.h>
#include <math.h>

using namespace nvcuda;

#define N_NODES  100000
#define N_EDGES  1600000
#define NH       128
#define N_GRAPHS 512
#define N_CLASS  10
#define SCAN_B   1024
#define SCAN_G   98

// -------- scratch (device globals; no allocation allowed) --------
__device__ __nv_bfloat16 g_h1[N_NODES * NH];  // dinv-prescaled x@W1 (bf16)
__device__ __nv_bfloat16 g_h2[N_NODES * NH];  // dinv-prescaled BN/ReLU out (bf16)
__device__ __nv_bfloat16 g_W1h[NH * NH];      // W1 in bf16
__device__ float g_bnA[NH];                   // gamma / sqrt(1+eps)
__device__ float g_bnB[NH];                   // b1*bnA + beta
__device__ float g_dinv[N_NODES];
__device__ int   g_deg[N_NODES];              // 1 + in-degree
__device__ int   g_rowStart[N_NODES];
__device__ int   g_cursor[N_NODES];
__device__ int   g_esrc[N_EDGES];             // edge sources grouped by dst
__device__ int   g_bsum[128];
__device__ int   g_boff[128];
__device__ float g_sums[N_GRAPHS * NH];
__device__ int   g_cnt[N_GRAPHS];

// ================= setup =================
__global__ void k_init0() {
    int i = blockIdx.x * blockDim.x + threadIdx.x;
    if (i < N_NODES) g_deg[i] = 1;
    if (i < N_GRAPHS * NH) g_sums[i] = 0.f;
    if (i < N_GRAPHS) g_cnt[i] = 0;
}

__global__ void k_count(const int* __restrict__ dst) {
    int e = blockIdx.x * blockDim.x + threadIdx.x;
    if (e < N_EDGES) atomicAdd(&g_deg[dst[e]], 1);
}

__global__ void k_dinv(const int* __restrict__ batch) {
    int i = blockIdx.x * blockDim.x + threadIdx.x;
    if (i < N_NODES) {
        g_dinv[i] = rsqrtf((float)g_deg[i]);
        atomicAdd(&g_cnt[batch[i]], 1);
    }
}

__global__ void k_scanA() {
    __shared__ int s[SCAN_B];
    int t = threadIdx.x;
    int i = blockIdx.x * SCAN_B + t;
    int v = (i < N_NODES) ? (g_deg[i] - 1) : 0;
    s[t] = v;
    __syncthreads();
    for (int off = 1; off < SCAN_B; off <<= 1) {
        int add = (t >= off) ? s[t - off] : 0;
        __syncthreads();
        s[t] += add;
        __syncthreads();
    }
    if (i < N_NODES) g_rowStart[i] = s[t] - v;
    if (t == SCAN_B - 1) g_bsum[blockIdx.x] = s[t];
}

__global__ void k_scanB() {
    __shared__ int s[128];
    int t = threadIdx.x;
    int v = (t < SCAN_G) ? g_bsum[t] : 0;
    s[t] = v;
    __syncthreads();
    for (int off = 1; off < 128; off <<= 1) {
        int add = (t >= off) ? s[t - off] : 0;
        __syncthreads();
        s[t] += add;
        __syncthreads();
    }
    if (t < SCAN_G) g_boff[t] = s[t] - v;   // exclusive
}

__global__ void k_scanC() {
    int i = blockIdx.x * SCAN_B + threadIdx.x;
    if (i < N_NODES) {
        int rs = g_rowStart[i] + g_boff[blockIdx.x];
        g_rowStart[i] = rs;
        g_cursor[i]   = rs;
    }
}

__global__ void k_fill(const int* __restrict__ srcp, const int* __restrict__ dstp) {
    int e = blockIdx.x * blockDim.x + threadIdx.x;
    if (e < N_EDGES) {
        int s = srcp[e], d = dstp[e];
        int pos = atomicAdd(&g_cursor[d], 1);
        g_esrc[pos] = s;
    }
}

// ============ W1 fp32 -> bf16, plus BN constant prep ============
__global__ void k_wconv(const float* __restrict__ W, const float* __restrict__ b1,
                        const float* __restrict__ gamma, const float* __restrict__ beta) {
    int i = blockIdx.x * blockDim.x + threadIdx.x;
    if (i < NH * NH) g_W1h[i] = __float2bfloat16_rn(W[i]);
    if (i < NH) {
        float a = gamma[i] * rsqrtf(1.0f + 1e-5f);
        g_bnA[i] = a;
        g_bnB[i] = b1[i] * a + beta[i];
    }
}

// ==== GEMM1 (bf16 tensor cores): g_h1 = dinv * (bf16(x) @ bf16(W1)) ====
__global__ void k_gemmT(const float* __restrict__ A) {
    __shared__ __align__(16) char smemraw[49152];
    __nv_bfloat16* sA = (__nv_bfloat16*)smemraw;             // 64 x 128
    __nv_bfloat16* sW = (__nv_bfloat16*)(smemraw + 16384);   // 128 x 128
    float*         sC = (float*)smemraw;                     // epilogue reuse
    int t = threadIdx.x;
    int w = t >> 5;
    long row0 = (long)blockIdx.x * 64;

    const int4* Wh4 = (const int4*)g_W1h;
    int4* sW4 = (int4*)sW;
    for (int i = t; i < 2048; i += 128) sW4[i] = Wh4[i];

    const float4* A4 = (const float4*)A;
    __nv_bfloat162* sA2 = (__nv_bfloat162*)sA;
    for (int i = t; i < 2048; i += 128) {
        int r = i >> 5, c = i & 31;
        long rg = row0 + r; if (rg >= N_NODES) rg = N_NODES - 1;
        float4 v = A4[rg * 32 + c];
        sA2[r * 64 + c * 2]     = __floats2bfloat162_rn(v.x, v.y);
        sA2[r * 64 + c * 2 + 1] = __floats2bfloat162_rn(v.z, v.w);
    }
    __syncthreads();

    wmma::fragment<wmma::accumulator, 16, 16, 16, float> cf[8];
#pragma unroll
    for (int n = 0; n < 8; n++) wmma::fill_fragment(cf[n], 0.f);
#pragma unroll
    for (int k0 = 0; k0 < 8; k0++) {
        wmma::fragment<wmma::matrix_a, 16, 16, 16, __nv_bfloat16, wmma::row_major> af;
        wmma::load_matrix_sync(af, sA + (w * 16) * 128 + k0 * 16, 128);
#pragma unroll
        for (int n = 0; n < 8; n++) {
            wmma::fragment<wmma::matrix_b, 16, 16, 16, __nv_bfloat16, wmma::row_major> bf;
            wmma::load_matrix_sync(bf, sW + (k0 * 16) * 128 + n * 16, 128);
            wmma::mma_sync(cf[n], af, bf, cf[n]);
        }
    }
    __syncthreads();
#pragma unroll
    for (int n = 0; n < 8; n++)
        wmma::store_matrix_sync(sC + (w * 16) * 128 + n * 16, cf[n], 128, wmma::mem_row_major);
    __syncthreads();

    __nv_bfloat162* out2 = (__nv_bfloat162*)g_h1;
    const float2* sC2 = (const float2*)sC;
    for (int i = t; i < 64 * 64; i += 128) {
        int r = i >> 6, c = i & 63;
        long rg = row0 + r;
        if (rg < N_NODES) {
            float dv = g_dinv[rg];
            float2 v = sC2[r * 64 + c];
            out2[rg * 64 + c] = __floats2bfloat162_rn(v.x * dv, v.y * dv);
        }
    }
}

// -------- gather helpers: bf16 expansion via bit ops (alu pipe, no F2F) --------
__device__ __forceinline__ void accb8(float* acc, int4 raw) {
    unsigned* u = (unsigned*)&raw;
#pragma unroll
    for (int k = 0; k < 4; k++) {
        acc[2 * k]     += __int_as_float(u[k] << 16);
        acc[2 * k + 1] += __int_as_float(u[k] & 0xFFFF0000u);
    }
}

// Aggregate node d's prescaled row-sum into acc[8] (lane li of half `half`).
// acc = sum of h_scaled over in-neighbors + self; caller multiplies by dinv[d].
__device__ __forceinline__ void gather_node(const int4* in4, int d, int half, int li,
                                            float* acc) {
    int start = g_rowStart[d];
    int len   = g_deg[d] - 1;
    if (half == 0) {
        int4 raw = in4[(long)d * 16 + li];
        unsigned* u = (unsigned*)&raw;
#pragma unroll
        for (int k = 0; k < 4; k++) {
            acc[2 * k]     = __int_as_float(u[k] << 16);
            acc[2 * k + 1] = __int_as_float(u[k] & 0xFFFF0000u);
        }
    } else {
#pragma unroll
        for (int k = 0; k < 8; k++) acc[k] = 0.f;
    }
    const int* ep = g_esrc + start;
    int j = half;
    for (; j + 6 < len; j += 8) {
        int s0 = ep[j],     s1 = ep[j + 2];
        int s2 = ep[j + 4], s3 = ep[j + 6];
        int4 r0 = in4[(long)s0 * 16 + li];
        int4 r1 = in4[(long)s1 * 16 + li];
        int4 r2 = in4[(long)s2 * 16 + li];
        int4 r3 = in4[(long)s3 * 16 + li];
        accb8(acc, r0);
        accb8(acc, r1);
        accb8(acc, r2);
        accb8(acc, r3);
    }
    for (; j < len; j += 2) {
        int4 r = in4[(long)ep[j] * 16 + li];
        accb8(acc, r);
    }
#pragma unroll
    for (int k = 0; k < 8; k++)
        acc[k] += __shfl_down_sync(0xffffffffu, acc[k], 16);
}

// ======= gather layer 1: agg -> *dinv -> BN(+b1) -> ReLU -> *dinv -> g_h2 =======
__global__ void __launch_bounds__(256, 4)
k_gather1() {
    int d = blockIdx.x * 8 + (threadIdx.x >> 5);
    int lane = threadIdx.x & 31;
    int half = lane >> 4, li = lane & 15;
    if (d >= N_NODES) return;
    float acc[8];
    gather_node((const int4*)g_h1, d, half, li, acc);
    if (half == 0) {
        float dv = g_dinv[d];
        int c8 = li * 8;
        float4 A0 = *(const float4*)&g_bnA[c8], A1 = *(const float4*)&g_bnA[c8 + 4];
        float4 B0 = *(const float4*)&g_bnB[c8], B1 = *(const float4*)&g_bnB[c8 + 4];
        float Aa[8] = {A0.x, A0.y, A0.z, A0.w, A1.x, A1.y, A1.z, A1.w};
        float Bb[8] = {B0.x, B0.y, B0.z, B0.w, B1.x, B1.y, B1.z, B1.w};
        __nv_bfloat162 o[4];
#pragma unroll
        for (int k = 0; k < 4; k++) {
            float v0 = fmaxf((acc[2 * k]     * dv) * Aa[2 * k]     + Bb[2 * k],     0.f) * dv;
            float v1 = fmaxf((acc[2 * k + 1] * dv) * Aa[2 * k + 1] + Bb[2 * k + 1], 0.f) * dv;
            o[k] = __floats2bfloat162_rn(v0, v1);
        }
        ((int4*)g_h2)[(long)d * 16 + li] = *(int4*)o;
    }
}

// ===== gather layer 2: agg -> *dinv -> pool into g_sums via smem staging =====
__global__ void __launch_bounds__(256, 4)
k_gather2(const int* __restrict__ batch) {
    __shared__ float sbuf[4][NH];
    __shared__ int sbase;
    int t = threadIdx.x;
    int w = t >> 5, lane = t & 31;
    int half = lane >> 4, li = lane & 15;
    int nb = blockIdx.x * 32;
    if (t == 0) sbase = batch[nb < N_NODES ? nb : N_NODES - 1];
    for (int i = t; i < 4 * NH; i += 256) ((float*)sbuf)[i] = 0.f;
    __syncthreads();
    int base = sbase;
    const int4* in4 = (const int4*)g_h2;

    for (int i = 0; i < 4; i++) {
        int d = nb + w * 4 + i;
        if (d >= N_NODES) break;
        float acc[8];
        gather_node(in4, d, half, li, acc);
        if (half == 0) {
            float dv = g_dinv[d];
            int b = batch[d];
            int slot = b - base;
            int c8 = li * 8;
            if (slot >= 0 && slot < 4) {
#pragma unroll
                for (int k = 0; k < 8; k++) atomicAdd(&sbuf[slot][c8 + k], acc[k] * dv);
            } else {
#pragma unroll
                for (int k = 0; k < 8; k++) atomicAdd(&g_sums[b * NH + c8 + k], acc[k] * dv);
            }
        }
    }
    __syncthreads();
    for (int i = t; i < 4 * NH; i += 256) {
        float v = ((float*)sbuf)[i];
        int slot = i >> 7, c = i & 127;
        int b = base + slot;
        if (v != 0.f && b < N_GRAPHS) atomicAdd(&g_sums[b * NH + c], v);
    }
}

// ==== final: g = (P @ W2)/cnt + b2 ; out = log_softmax(g @ clsW + clsb) ====
__global__ void k_final(const float* __restrict__ W2, const float* __restrict__ b2,
                        const float* __restrict__ clsW, const float* __restrict__ clsb,
                        float* __restrict__ out) {
    int gph = blockIdx.x;
    int t = threadIdx.x;
    __shared__ float sp[NH];
    __shared__ float sg[NH];
    __shared__ float sl[N_CLASS];
    __shared__ float lse;
    float cnt = fmaxf((float)g_cnt[gph], 1.0f);
    sp[t] = g_sums[gph * NH + t];
    __syncthreads();
    float acc = 0.f;
#pragma unroll 8
    for (int k = 0; k < NH; k++) acc += sp[k] * W2[k * NH + t];
    float gv = acc / cnt + b2[t];
    sg[t] = gv;
    out[N_GRAPHS * N_CLASS + gph * NH + t] = gv;
    __syncthreads();
    if (t < N_CLASS) {
        float a2 = clsb[t];
        for (int k = 0; k < NH; k++) a2 += sg[k] * clsW[k * N_CLASS + t];
        sl[t] = a2;
    }
    __syncthreads();
    if (t == 0) {
        float m = sl[0];
        for (int i = 1; i < N_CLASS; i++) m = fmaxf(m, sl[i]);
        float s = 0.f;
        for (int i = 0; i < N_CLASS; i++) s += expf(sl[i] - m);
        lse = m + logf(s);
    }
    __syncthreads();
    if (t < N_CLASS) out[gph * N_CLASS + t] = sl[t] - lse;
}

extern "C" void kernel_launch(void* const* d_in, const int* in_sizes, int n_in,
                              void* d_out, int out_size) {
    const float* x     = (const float*)d_in[0];
    const int*   ei    = (const int*)d_in[1];
    const int*   batch = (const int*)d_in[2];
    const float* W1    = (const float*)d_in[3];
    const float* b1    = (const float*)d_in[4];
    const float* gamma = (const float*)d_in[5];
    const float* beta  = (const float*)d_in[6];
    const float* W2    = (const float*)d_in[7];
    const float* b2    = (const float*)d_in[8];
    const float* clsW  = (const float*)d_in[9];
    const float* clsb  = (const float*)d_in[10];
    float* out = (float*)d_out;

    const int* srcp = ei;
    const int* dstp = ei + N_EDGES;

    const int TPB = 256;
    int nodeBlocks = (N_NODES + TPB - 1) / TPB;
    int edgeBlocks = (N_EDGES + TPB - 1) / TPB;

    static cudaStream_t s1 = []() {
        cudaStream_t s; cudaStreamCreateWithFlags(&s, cudaStreamNonBlocking); return s;
    }();
    static cudaEvent_t evDeg = []() {
        cudaEvent_t e; cudaEventCreateWithFlags(&e, cudaEventDisableTiming); return e;
    }();
    static cudaEvent_t evFill = []() {
        cudaEvent_t e; cudaEventCreateWithFlags(&e, cudaEventDisableTiming); return e;
    }();

    // main: degree + dinv (needed by both branches)
    k_init0<<<nodeBlocks, TPB>>>();
    k_count<<<edgeBlocks, TPB>>>(dstp);
    k_dinv<<<nodeBlocks, TPB>>>(batch);
    cudaEventRecord(evDeg, 0);

    // s1: CSR build (scan + fill) — independent of GEMM
    cudaStreamWaitEvent(s1, evDeg, 0);
    k_scanA<<<SCAN_G, SCAN_B, 0, s1>>>();
    k_scanB<<<1, 128, 0, s1>>>();
    k_scanC<<<SCAN_G, SCAN_B, 0, s1>>>();
    k_fill<<<edgeBlocks, TPB, 0, s1>>>(srcp, dstp);
    cudaEventRecord(evFill, s1);

    // main: bf16 tensor-core GEMM with dinv-prescaled epilogue
    k_wconv<<<64, 256>>>(W1, b1, gamma, beta);
    k_gemmT<<<(N_NODES + 63) / 64, 128>>>(x);

    // join, then gathers + final
    cudaStreamWaitEvent(0, evFill, 0);
    k_gather1<<<(N_NODES + 7) / 8, 256>>>();
    k_gather2<<<(N_NODES + 31) / 32, 256>>>(batch);
    k_final<<<N_GRAPHS, NH>>>(W2, b2, clsW, clsb, out);
}